// round 1
// baseline (speedup 1.0000x reference)
#include <cuda_runtime.h>
#include <math.h>

// Problem dims (fixed by dataset)
constexpr int B_  = 32;
constexpr int CL_ = 1536;
constexpr int T_  = 256;
constexpr int MI_ = 512;
constexpr int CG_ = 192;
constexpr int NT_ = B_ * T_;   // 8192

// ---------------- scratch (static __device__ — no allocs allowed) ----------
__device__ float g_Y1[(size_t)B_ * MI_ * T_];   // conv1 output
__device__ float g_H [(size_t)B_ * MI_ * T_];   // shortcut, then h (in place)
__device__ float g_Lh[(size_t)B_ * MI_ * T_];   // LayerNorm'd + L2-normalized locals
__device__ float g_scale[MI_], g_shift[MI_];    // BN folded affine
__device__ float g_yg[B_ * MI_];                // global conv1
__device__ float g_hg[B_ * MI_];                // global shortcut -> h (in place)
__device__ float g_gscale[MI_], g_gshift[MI_];
__device__ float g_Ghat[B_ * MI_];              // normalized globals
__device__ float g_uall[(size_t)B_ * NT_];      // raw dot(g_n, lhat_{m,t})

// ---------------- helpers ---------------------------------------------------
__device__ __forceinline__ float blockReduceSum(float v, float* red) {
    __syncthreads();
    #pragma unroll
    for (int o = 16; o; o >>= 1) v += __shfl_xor_sync(0xffffffffu, v, o);
    int lane = threadIdx.x & 31, wid = threadIdx.x >> 5;
    if (lane == 0) red[wid] = v;
    __syncthreads();
    if (threadIdx.x < 32) {
        float t = (threadIdx.x < (blockDim.x >> 5)) ? red[threadIdx.x] : 0.f;
        #pragma unroll
        for (int o = 4; o; o >>= 1) t += __shfl_xor_sync(0xffffffffu, t, o);
        if (threadIdx.x == 0) red[0] = t;
    }
    __syncthreads();
    return red[0];
}

// ---------------- GEMM1: Y1 = W1 @ x,  H = Ws @ x  (x read once) ------------
// out[o, (b,t)] ; block: 64 o x 64 t for one b ; K = 1536, BK = 16
__global__ __launch_bounds__(256) void gemm1_dual(
    const float* __restrict__ x, const float* __restrict__ W1,
    const float* __restrict__ Ws)
{
    const int t0 = blockIdx.x * 64;
    const int o0 = blockIdx.y * 64;
    const int b  = blockIdx.z;

    __shared__ float sX[16][68];   // [k][t]
    __shared__ float sA[16][68];   // W1 [k][o]
    __shared__ float sB[16][68];   // Ws [k][o]

    const int tid = threadIdx.x;
    const int ty = tid >> 4, tx = tid & 15;

    float acc1[4][4] = {}, acc2[4][4] = {};

    const int xk = tid >> 4;            // 0..15
    const int xt = (tid & 15) * 4;      // 0..60
    const int wo = tid >> 2;            // 0..63
    const int wk = (tid & 3) * 4;       // 0..12

    const float* xp  = x  + ((size_t)b * CL_ + xk) * T_ + t0 + xt;
    const float* w1p = W1 + (size_t)(o0 + wo) * CL_ + wk;
    const float* wsp = Ws + (size_t)(o0 + wo) * CL_ + wk;

    for (int c0 = 0; c0 < CL_; c0 += 16) {
        float4 xv = *(const float4*)xp;
        float4 a1 = *(const float4*)w1p;
        float4 a2 = *(const float4*)wsp;
        __syncthreads();
        *(float4*)&sX[xk][xt] = xv;
        sA[wk + 0][wo] = a1.x; sA[wk + 1][wo] = a1.y;
        sA[wk + 2][wo] = a1.z; sA[wk + 3][wo] = a1.w;
        sB[wk + 0][wo] = a2.x; sB[wk + 1][wo] = a2.y;
        sB[wk + 2][wo] = a2.z; sB[wk + 3][wo] = a2.w;
        __syncthreads();
        #pragma unroll
        for (int kk = 0; kk < 16; kk++) {
            float4 av1 = *(const float4*)&sA[kk][ty * 4];
            float4 av2 = *(const float4*)&sB[kk][ty * 4];
            float4 bx  = *(const float4*)&sX[kk][tx * 4];
            float a1r[4] = {av1.x, av1.y, av1.z, av1.w};
            float a2r[4] = {av2.x, av2.y, av2.z, av2.w};
            float br[4]  = {bx.x, bx.y, bx.z, bx.w};
            #pragma unroll
            for (int i = 0; i < 4; i++)
                #pragma unroll
                for (int j = 0; j < 4; j++) {
                    acc1[i][j] = fmaf(a1r[i], br[j], acc1[i][j]);
                    acc2[i][j] = fmaf(a2r[i], br[j], acc2[i][j]);
                }
        }
        xp += 16 * T_; w1p += 16; wsp += 16;
    }

    size_t base = ((size_t)b * MI_ + o0 + ty * 4) * T_ + t0 + tx * 4;
    #pragma unroll
    for (int i = 0; i < 4; i++) {
        *(float4*)&g_Y1[base + (size_t)i * T_] =
            make_float4(acc1[i][0], acc1[i][1], acc1[i][2], acc1[i][3]);
        *(float4*)&g_H[base + (size_t)i * T_] =
            make_float4(acc2[i][0], acc2[i][1], acc2[i][2], acc2[i][3]);
    }
}

// ---------------- BatchNorm stats over (b,t) per channel o ------------------
__global__ __launch_bounds__(256) void bn_stats(
    const float* __restrict__ g1, const float* __restrict__ b1)
{
    const int o = blockIdx.x;
    const int tid = threadIdx.x;
    __shared__ float red[32];
    float s = 0.f, s2 = 0.f;
    const float* p = g_Y1 + (size_t)o * T_ + tid;
    #pragma unroll
    for (int b = 0; b < B_; b++) {
        float v = p[(size_t)b * MI_ * T_];
        s += v; s2 += v * v;
    }
    s  = blockReduceSum(s,  red);
    s2 = blockReduceSum(s2, red);
    if (tid == 0) {
        float mu  = s  * (1.f / 8192.f);
        float var = s2 * (1.f / 8192.f) - mu * mu;
        float r   = rsqrtf(var + 1e-5f);
        float sc  = r * g1[o];
        g_scale[o] = sc;
        g_shift[o] = fmaf(-mu, sc, b1[o]);
    }
}

// ---------------- GEMM2: h = W2 @ relu(BN(Y1)) + b2 + shortcut (in H) -------
__global__ __launch_bounds__(256) void gemm2_fused(
    const float* __restrict__ W2, const float* __restrict__ b2)
{
    const int t0 = blockIdx.x * 64;
    const int p0 = blockIdx.y * 64;
    const int b  = blockIdx.z;

    __shared__ float sX[16][68];   // relu(bn(Y1)) [k=o][t]
    __shared__ float sA[16][68];   // W2 [k=o][p]

    const int tid = threadIdx.x;
    const int ty = tid >> 4, tx = tid & 15;
    float acc[4][4] = {};

    const int xk = tid >> 4;
    const int xt = (tid & 15) * 4;
    const int wo = tid >> 2;
    const int wk = (tid & 3) * 4;

    const float* yp = g_Y1 + ((size_t)b * MI_ + xk) * T_ + t0 + xt;
    const float* wp = W2 + (size_t)(p0 + wo) * MI_ + wk;

    for (int c0 = 0; c0 < MI_; c0 += 16) {
        float4 yv = *(const float4*)yp;
        float  sc = g_scale[c0 + xk];
        float  sh = g_shift[c0 + xk];
        yv.x = fmaxf(fmaf(yv.x, sc, sh), 0.f);
        yv.y = fmaxf(fmaf(yv.y, sc, sh), 0.f);
        yv.z = fmaxf(fmaf(yv.z, sc, sh), 0.f);
        yv.w = fmaxf(fmaf(yv.w, sc, sh), 0.f);
        float4 a1 = *(const float4*)wp;
        __syncthreads();
        *(float4*)&sX[xk][xt] = yv;
        sA[wk + 0][wo] = a1.x; sA[wk + 1][wo] = a1.y;
        sA[wk + 2][wo] = a1.z; sA[wk + 3][wo] = a1.w;
        __syncthreads();
        #pragma unroll
        for (int kk = 0; kk < 16; kk++) {
            float4 av = *(const float4*)&sA[kk][ty * 4];
            float4 bx = *(const float4*)&sX[kk][tx * 4];
            float ar[4] = {av.x, av.y, av.z, av.w};
            float br[4] = {bx.x, bx.y, bx.z, bx.w};
            #pragma unroll
            for (int i = 0; i < 4; i++)
                #pragma unroll
                for (int j = 0; j < 4; j++)
                    acc[i][j] = fmaf(ar[i], br[j], acc[i][j]);
        }
        yp += 16 * T_; wp += 16;
    }

    size_t base = ((size_t)b * MI_ + p0 + ty * 4) * T_ + t0 + tx * 4;
    #pragma unroll
    for (int i = 0; i < 4; i++) {
        float bias = b2[p0 + ty * 4 + i];
        float4* hp = (float4*)&g_H[base + (size_t)i * T_];
        float4 h = *hp;
        h.x += acc[i][0] + bias; h.y += acc[i][1] + bias;
        h.z += acc[i][2] + bias; h.w += acc[i][3] + bias;
        *hp = h;
    }
}

// ---------------- LayerNorm(channel) + L2 normalize -> Lhat -----------------
// block: one b, 32 t's; threads (ty=0..7 over p, tx=0..31 over t)
__global__ __launch_bounds__(256) void ln_local(
    const float* __restrict__ lng, const float* __restrict__ lnb)
{
    const int b  = blockIdx.y;
    const int t0 = blockIdx.x * 32;
    const int tx = threadIdx.x & 31;
    const int ty = threadIdx.x >> 5;

    const float* base = g_H + (size_t)b * MI_ * T_ + t0 + tx;
    __shared__ float r1[8][33], r2[8][33];
    __shared__ float mu_s[32], rs_s[32], rn_s[32];

    float s = 0.f, s2 = 0.f;
    for (int p = ty; p < MI_; p += 8) {
        float v = base[(size_t)p * T_];
        s += v; s2 += v * v;
    }
    r1[ty][tx] = s; r2[ty][tx] = s2;
    __syncthreads();
    if (ty == 0) {
        float a = 0.f, c = 0.f;
        #pragma unroll
        for (int i = 0; i < 8; i++) { a += r1[i][tx]; c += r2[i][tx]; }
        float mu  = a * (1.f / 512.f);
        float var = c * (1.f / 512.f) - mu * mu;
        mu_s[tx] = mu;
        rs_s[tx] = rsqrtf(var + 1e-5f);
    }
    __syncthreads();
    float mu = mu_s[tx], rs = rs_s[tx];

    float n2 = 0.f;
    for (int p = ty; p < MI_; p += 8) {
        float v = base[(size_t)p * T_];
        float z = fmaf((v - mu) * rs, lng[p], lnb[p]);
        n2 += z * z;
    }
    __syncthreads();
    r1[ty][tx] = n2;
    __syncthreads();
    if (ty == 0) {
        float a = 0.f;
        #pragma unroll
        for (int i = 0; i < 8; i++) a += r1[i][tx];
        rn_s[tx] = 1.f / sqrtf(a);
    }
    __syncthreads();
    float rn = rn_s[tx];

    float* ob = g_Lh + (size_t)b * MI_ * T_ + t0 + tx;
    for (int p = ty; p < MI_; p += 8) {
        float v = base[(size_t)p * T_];
        float z = fmaf((v - mu) * rs, lng[p], lnb[p]);
        ob[(size_t)p * T_] = z * rn;
    }
}

// ---------------- Global path (tiny: B=32, T=1) -----------------------------
__global__ __launch_bounds__(256) void g_mlp1(
    const float* __restrict__ gx, const float* __restrict__ gW1,
    const float* __restrict__ gWs)
{
    const int b = blockIdx.x, tid = threadIdx.x;
    __shared__ float xs[CG_];
    if (tid < CG_) xs[tid] = gx[b * CG_ + tid];
    __syncthreads();
    for (int o = tid; o < MI_; o += 256) {
        const float* w1 = gW1 + (size_t)o * CG_;
        const float* ws = gWs + (size_t)o * CG_;
        float a = 0.f, c = 0.f;
        #pragma unroll 4
        for (int k = 0; k < CG_; k++) {
            float xv = xs[k];
            a = fmaf(w1[k], xv, a);
            c = fmaf(ws[k], xv, c);
        }
        g_yg[b * MI_ + o] = a;
        g_hg[b * MI_ + o] = c;
    }
}

__global__ void g_bn(const float* __restrict__ gg1, const float* __restrict__ gb1)
{
    const int o = threadIdx.x;   // 512 threads
    float s = 0.f, s2 = 0.f;
    #pragma unroll
    for (int b = 0; b < B_; b++) {
        float v = g_yg[b * MI_ + o];
        s += v; s2 += v * v;
    }
    float mu  = s  * (1.f / 32.f);
    float var = s2 * (1.f / 32.f) - mu * mu;
    float r   = rsqrtf(var + 1e-5f);
    float sc  = r * gg1[o];
    g_gscale[o] = sc;
    g_gshift[o] = fmaf(-mu, sc, gb1[o]);
}

__global__ __launch_bounds__(256) void g_mlp2(
    const float* __restrict__ gW2, const float* __restrict__ gb2)
{
    const int b = blockIdx.x, tid = threadIdx.x;
    __shared__ float a[MI_];
    for (int o = tid; o < MI_; o += 256)
        a[o] = fmaxf(fmaf(g_yg[b * MI_ + o], g_gscale[o], g_gshift[o]), 0.f);
    __syncthreads();
    for (int p = tid; p < MI_; p += 256) {
        const float* w = gW2 + (size_t)p * MI_;
        float acc = 0.f;
        #pragma unroll 4
        for (int k = 0; k < MI_; k++) acc = fmaf(w[k], a[k], acc);
        g_hg[b * MI_ + p] = acc + gb2[p] + g_hg[b * MI_ + p];
    }
}

__global__ __launch_bounds__(256) void g_ln(
    const float* __restrict__ glng, const float* __restrict__ glnb)
{
    const int b = blockIdx.x, tid = threadIdx.x;
    __shared__ float red[32];
    __shared__ float sh;
    float v0 = g_hg[b * MI_ + tid];
    float v1 = g_hg[b * MI_ + tid + 256];
    float s = blockReduceSum(v0 + v1, red);
    if (tid == 0) sh = s * (1.f / 512.f);
    __syncthreads();
    float mu = sh;
    float d0 = v0 - mu, d1 = v1 - mu;
    float q = blockReduceSum(d0 * d0 + d1 * d1, red);
    if (tid == 0) sh = rsqrtf(q * (1.f / 512.f) + 1e-5f);
    __syncthreads();
    float rs = sh;
    float z0 = fmaf(d0 * rs, glng[tid],       glnb[tid]);
    float z1 = fmaf(d1 * rs, glng[tid + 256], glnb[tid + 256]);
    float n2 = blockReduceSum(z0 * z0 + z1 * z1, red);
    if (tid == 0) sh = 1.f / sqrtf(n2);
    __syncthreads();
    float rn = sh;
    g_Ghat[b * MI_ + tid]       = z0 * rn;
    g_Ghat[b * MI_ + tid + 256] = z1 * rn;
}

// ---------------- u_all[n, m*T+t] = dot(Ghat[n], Lhat[m,:,t]) ---------------
__global__ __launch_bounds__(256) void gemm_uall()
{
    const int t0 = blockIdx.x * 64;
    const int m  = blockIdx.y;
    __shared__ float sG[32][36];   // [n][k]
    __shared__ float sL[32][68];   // [k][t]
    const int tid = threadIdx.x;
    const int ty = tid >> 4, tx = tid & 15;
    float acc[2][4] = {};

    for (int d0 = 0; d0 < MI_; d0 += 32) {
        __syncthreads();
        {
            int n = tid >> 3, k4 = (tid & 7) * 4;
            *(float4*)&sG[n][k4] = *(const float4*)&g_Ghat[n * MI_ + d0 + k4];
        }
        {
            int k = tid >> 4, c4 = (tid & 15) * 4;
            *(float4*)&sL[k][c4] =
                *(const float4*)&g_Lh[((size_t)m * MI_ + d0 + k) * T_ + t0 + c4];
            *(float4*)&sL[k + 16][c4] =
                *(const float4*)&g_Lh[((size_t)m * MI_ + d0 + k + 16) * T_ + t0 + c4];
        }
        __syncthreads();
        #pragma unroll
        for (int kk = 0; kk < 32; kk++) {
            float a0 = sG[ty * 2][kk], a1 = sG[ty * 2 + 1][kk];
            float4 bv = *(const float4*)&sL[kk][tx * 4];
            acc[0][0] = fmaf(a0, bv.x, acc[0][0]);
            acc[0][1] = fmaf(a0, bv.y, acc[0][1]);
            acc[0][2] = fmaf(a0, bv.z, acc[0][2]);
            acc[0][3] = fmaf(a0, bv.w, acc[0][3]);
            acc[1][0] = fmaf(a1, bv.x, acc[1][0]);
            acc[1][1] = fmaf(a1, bv.y, acc[1][1]);
            acc[1][2] = fmaf(a1, bv.z, acc[1][2]);
            acc[1][3] = fmaf(a1, bv.w, acc[1][3]);
        }
    }
    #pragma unroll
    for (int i = 0; i < 2; i++) {
        *(float4*)&g_uall[(size_t)(ty * 2 + i) * NT_ + m * T_ + t0 + tx * 4] =
            make_float4(acc[i][0], acc[i][1], acc[i][2], acc[i][3]);
    }
}

// ---------------- loss ------------------------------------------------------
__global__ void zero_out(float* out) { *out = 0.f; }

__global__ __launch_bounds__(256) void loss_kernel(float* __restrict__ out)
{
    const int n = blockIdx.x, tid = threadIdx.x;
    const float* u = g_uall + (size_t)n * NT_;
    __shared__ float red[32];
    __shared__ float sh;

    // max over negatives (exclude whole diag block m == n)
    float m = -1e30f;
    for (int j = tid; j < NT_; j += 256)
        if ((j >> 8) != n) m = fmaxf(m, u[j]);
    #pragma unroll
    for (int o = 16; o; o >>= 1) m = fmaxf(m, __shfl_xor_sync(0xffffffffu, m, o));
    int lane = tid & 31, wid = tid >> 5;
    if (lane == 0) red[wid] = m;
    __syncthreads();
    if (tid < 32) {
        float v = (tid < 8) ? red[tid] : -1e30f;
        #pragma unroll
        for (int o = 4; o; o >>= 1) v = fmaxf(v, __shfl_xor_sync(0xffffffffu, v, o));
        if (tid == 0) sh = v;
    }
    __syncthreads();
    float M = sh;

    float s = 0.f;
    for (int j = tid; j < NT_; j += 256)
        if ((j >> 8) != n) s += expf(u[j] - M);
    s = blockReduceSum(s, red);
    if (tid == 0) sh = M + logf(s);
    __syncthreads();
    float A = sh;   // LSE of negatives for this n

    // positives: one per t (exactly 256 threads)
    float p  = u[n * T_ + tid] / 0.07f;
    float mx = fmaxf(p, A);
    float c  = p - (mx + logf(expf(p - mx) + expf(A - mx)));
    c = blockReduceSum(c, red);
    if (tid == 0) atomicAdd(out, -c / (float)NT_);
}

// ---------------- launch ----------------------------------------------------
extern "C" void kernel_launch(void* const* d_in, const int* in_sizes, int n_in,
                              void* d_out, int out_size)
{
    const float* x    = (const float*)d_in[0];
    const float* gx   = (const float*)d_in[1];
    const float* lW1  = (const float*)d_in[2];
    const float* lg1  = (const float*)d_in[3];
    const float* lb1  = (const float*)d_in[4];
    const float* lW2  = (const float*)d_in[5];
    const float* lb2  = (const float*)d_in[6];
    const float* lWs  = (const float*)d_in[7];
    const float* llng = (const float*)d_in[8];
    const float* llnb = (const float*)d_in[9];
    const float* gW1  = (const float*)d_in[10];
    const float* gg1  = (const float*)d_in[11];
    const float* gb1  = (const float*)d_in[12];
    const float* gW2  = (const float*)d_in[13];
    const float* gb2  = (const float*)d_in[14];
    const float* gWs  = (const float*)d_in[15];
    const float* glng = (const float*)d_in[16];
    const float* glnb = (const float*)d_in[17];
    float* out = (float*)d_out;

    zero_out<<<1, 1>>>(out);

    // local path
    gemm1_dual<<<dim3(4, 8, 32), 256>>>(x, lW1, lWs);
    bn_stats<<<512, 256>>>(lg1, lb1);
    gemm2_fused<<<dim3(4, 8, 32), 256>>>(lW2, lb2);
    ln_local<<<dim3(8, 32), 256>>>(llng, llnb);

    // global path (tiny)
    g_mlp1<<<32, 256>>>(gx, gW1, gWs);
    g_bn<<<1, 512>>>(gg1, gb1);
    g_mlp2<<<32, 256>>>(gW2, gb2);
    g_ln<<<32, 256>>>(glng, glnb);

    // infonce
    gemm_uall<<<dim3(4, 32), 256>>>();
    loss_kernel<<<32, 256>>>(out);
}

// round 4
// speedup vs baseline: 1.3243x; 1.3243x over previous
#include <cuda_runtime.h>
#include <cuda_bf16.h>
#include <math.h>
#include <cstdint>

// Problem dims (fixed by dataset)
constexpr int B_  = 32;
constexpr int CL_ = 1536;
constexpr int T_  = 256;
constexpr int MI_ = 512;
constexpr int CG_ = 192;
constexpr int NT_ = B_ * T_;          // 8192
constexpr int KP1 = 3 * CL_;          // 4608  (split-bf16 extended K, GEMM1)
constexpr int KP2 = 3 * MI_;          // 1536  (GEMM2)

// ---------------- scratch (static __device__ — no allocs allowed) -----------
__device__ __nv_bfloat16 g_Xc [(size_t)NT_ * KP1];   // [bt][k'] B-operand GEMM1
__device__ __nv_bfloat16 g_Ac [(size_t)1024 * KP1];  // [W1;Ws] split A-operand
__device__ __nv_bfloat16 g_X2c[(size_t)NT_ * KP2];   // [bt][k'] B-operand GEMM2
__device__ __nv_bfloat16 g_A2c[(size_t)MI_ * KP2];   // W2 split
__device__ float g_Y1[(size_t)MI_ * NT_];            // conv1 out   [o][bt]
__device__ float g_Hs[(size_t)MI_ * NT_];            // shortcut    [o][bt]
__device__ float g_Hf[(size_t)MI_ * NT_];            // final h     [o][bt]
__device__ float g_Lh[(size_t)MI_ * NT_];            // normalized locals [d][bt]
__device__ float g_scale[MI_], g_shift[MI_];
__device__ float g_yg[B_ * MI_], g_hg[B_ * MI_];
__device__ float g_gscale[MI_], g_gshift[MI_];
__device__ float g_Ghat[B_ * MI_];
__device__ float g_uall[(size_t)B_ * NT_];

// ---------------- small helpers ----------------------------------------------
__device__ __forceinline__ uint32_t smem_u32(const void* p) {
    uint32_t a;
    asm("{ .reg .u64 t; cvta.to.shared.u64 t, %1; cvt.u32.u64 %0, t; }"
        : "=r"(a) : "l"(p));
    return a;
}
__device__ __forceinline__ void cp_async16(uint32_t saddr, const void* gaddr) {
    asm volatile("cp.async.cg.shared.global [%0], [%1], 16;"
                 :: "r"(saddr), "l"(gaddr) : "memory");
}
__device__ __forceinline__ void cp_commit() {
    asm volatile("cp.async.commit_group;" ::: "memory");
}
template<int N>
__device__ __forceinline__ void cp_wait() {
    asm volatile("cp.async.wait_group %0;" :: "n"(N) : "memory");
}
__device__ __forceinline__ void ldsm_x4(uint32_t* r, uint32_t addr) {
    asm volatile("ldmatrix.sync.aligned.m8n8.x4.shared.b16 {%0,%1,%2,%3}, [%4];"
                 : "=r"(r[0]), "=r"(r[1]), "=r"(r[2]), "=r"(r[3]) : "r"(addr));
}
__device__ __forceinline__ void mma_bf16(float* d, const uint32_t* a,
                                         uint32_t b0, uint32_t b1) {
    asm volatile("mma.sync.aligned.m16n8k16.row.col.f32.bf16.bf16.f32 "
                 "{%0,%1,%2,%3}, {%4,%5,%6,%7}, {%8,%9}, {%0,%1,%2,%3};"
                 : "+f"(d[0]), "+f"(d[1]), "+f"(d[2]), "+f"(d[3])
                 : "r"(a[0]), "r"(a[1]), "r"(a[2]), "r"(a[3]), "r"(b0), "r"(b1));
}

__device__ __forceinline__ float blockReduceSum(float v, float* red) {
    __syncthreads();
    #pragma unroll
    for (int o = 16; o; o >>= 1) v += __shfl_xor_sync(0xffffffffu, v, o);
    int lane = threadIdx.x & 31, wid = threadIdx.x >> 5;
    if (lane == 0) red[wid] = v;
    __syncthreads();
    if (threadIdx.x < 32) {
        float t = (threadIdx.x < (blockDim.x >> 5)) ? red[threadIdx.x] : 0.f;
        #pragma unroll
        for (int o = 4; o; o >>= 1) t += __shfl_xor_sync(0xffffffffu, t, o);
        if (threadIdx.x == 0) red[0] = t;
    }
    __syncthreads();
    return red[0];
}

// ---------------- operand prep ------------------------------------------------
// x [b][c][t] fp32 -> Xc [bt][k'] bf16 with k' regions: [hi, hi, lo]
__global__ __launch_bounds__(256) void split_x(const float* __restrict__ x)
{
    __shared__ float tile[64][65];
    const int b = blockIdx.z, c0 = blockIdx.y * 64, t0 = blockIdx.x * 64;
    const int tid = threadIdx.x;
    #pragma unroll
    for (int it = 0; it < 16; it++) {
        int i = it * 256 + tid, c = i >> 6, t = i & 63;
        tile[c][t] = x[((size_t)b * CL_ + c0 + c) * T_ + t0 + t];
    }
    __syncthreads();
    #pragma unroll
    for (int it = 0; it < 16; it++) {
        int i = it * 256 + tid, r = i >> 6, col = i & 63;
        float v = tile[col][r];
        __nv_bfloat16 hi = __float2bfloat16(v);
        __nv_bfloat16 lo = __float2bfloat16(v - __bfloat162float(hi));
        size_t row = (size_t)(b * T_ + t0 + r) * KP1;
        g_Xc[row + c0 + col]            = hi;
        g_Xc[row + CL_ + c0 + col]      = hi;
        g_Xc[row + 2 * CL_ + c0 + col]  = lo;
    }
}

// W1, Ws -> Ac [1024][k'] with k' regions: [hi, lo, hi]
__global__ __launch_bounds__(256) void split_wA(const float* __restrict__ W1,
                                                const float* __restrict__ Ws)
{
    const int r = blockIdx.x;
    for (int c = threadIdx.x; c < CL_; c += 256) {
        float v = (r < 512) ? W1[(size_t)r * CL_ + c] : Ws[(size_t)(r - 512) * CL_ + c];
        __nv_bfloat16 hi = __float2bfloat16(v);
        __nv_bfloat16 lo = __float2bfloat16(v - __bfloat162float(hi));
        size_t row = (size_t)r * KP1;
        g_Ac[row + c]            = hi;
        g_Ac[row + CL_ + c]      = lo;
        g_Ac[row + 2 * CL_ + c]  = hi;
    }
}

// relu(bn(Y1)) [o][bt] -> X2c [bt][k'] regions [hi, hi, lo]
__global__ __launch_bounds__(256) void split_y()
{
    __shared__ float tile[64][65];
    const int o0 = blockIdx.y * 64, q0 = blockIdx.x * 64;
    const int tid = threadIdx.x;
    #pragma unroll
    for (int it = 0; it < 16; it++) {
        int i = it * 256 + tid, c = i >> 6, t = i & 63;
        float v = g_Y1[(size_t)(o0 + c) * NT_ + q0 + t];
        tile[c][t] = fmaxf(fmaf(v, g_scale[o0 + c], g_shift[o0 + c]), 0.f);
    }
    __syncthreads();
    #pragma unroll
    for (int it = 0; it < 16; it++) {
        int i = it * 256 + tid, r = i >> 6, col = i & 63;
        float v = tile[col][r];
        __nv_bfloat16 hi = __float2bfloat16(v);
        __nv_bfloat16 lo = __float2bfloat16(v - __bfloat162float(hi));
        size_t row = (size_t)(q0 + r) * KP2;
        g_X2c[row + o0 + col]            = hi;
        g_X2c[row + MI_ + o0 + col]      = hi;
        g_X2c[row + 2 * MI_ + o0 + col]  = lo;
    }
}

// W2 -> A2c [512][k'] regions [hi, lo, hi]
__global__ __launch_bounds__(256) void split_w2(const float* __restrict__ W2)
{
    const int r = blockIdx.x;
    for (int c = threadIdx.x; c < MI_; c += 256) {
        float v = W2[(size_t)r * MI_ + c];
        __nv_bfloat16 hi = __float2bfloat16(v);
        __nv_bfloat16 lo = __float2bfloat16(v - __bfloat162float(hi));
        size_t row = (size_t)r * KP2;
        g_A2c[row + c]            = hi;
        g_A2c[row + MI_ + c]      = lo;
        g_A2c[row + 2 * MI_ + c]  = hi;
    }
}

// ---------------- HMMA GEMM (mma.sync bf16, fp32 accum) -----------------------
// D[m][n] = sum_k A[m][k] * B[n][k]   (both K-contiguous, "TN")
// MODE 1: A=g_Ac (1024 x KP1), B=g_Xc (8192 x KP1): rows<512 -> g_Y1 else g_Hs
// MODE 2: A=g_A2c (512 x KP2), B=g_X2c: D + bias + g_Hs -> g_Hf
// CTA: 128x128 tile, BK=32, 8 warps (warp tile 64x32), 3-stage cp.async.
constexpr int KPAD   = 80;                // bytes per 32-bf16 row (64B + 16B pad)
constexpr int STG_A  = 128 * KPAD;        // 10240
constexpr int STG_SZ = 2 * STG_A;         // 20480 per stage (A then B)
constexpr int NSTG   = 3;
constexpr int GEMM_SMEM = NSTG * STG_SZ;  // 61440

template<int MODE>
__global__ __launch_bounds__(256, 2) void gemm_mma(const float* __restrict__ bias)
{
    constexpr int KPRIME = (MODE == 1) ? KP1 : KP2;
    constexpr int ITERS  = KPRIME / 32;
    const __nv_bfloat16* __restrict__ A  = (MODE == 1) ? g_Ac : g_A2c;
    const __nv_bfloat16* __restrict__ Bm = (MODE == 1) ? g_Xc : g_X2c;

    extern __shared__ char smem[];
    const uint32_t sbase = smem_u32(smem);
    const int tid = threadIdx.x, wid = tid >> 5, lane = tid & 31;
    const int n0 = blockIdx.x * 128;
    const int m0 = blockIdx.y * 128;

    // cp.async mapping: 512 16B chunks per tile, 2 per thread per tile
    const int q0r = tid >> 2, q0c = tid & 3;          // chunk tid
    const int q1r = (tid + 256) >> 2, q1c = q0c;      // chunk tid+256

    auto load_stage = [&](int stg, int k0) {
        const uint32_t sa = sbase + stg * STG_SZ;
        const uint32_t sb = sa + STG_A;
        cp_async16(sa + q0r * KPAD + q0c * 16, A  + (size_t)(m0 + q0r) * KPRIME + k0 + q0c * 8);
        cp_async16(sa + q1r * KPAD + q1c * 16, A  + (size_t)(m0 + q1r) * KPRIME + k0 + q1c * 8);
        cp_async16(sb + q0r * KPAD + q0c * 16, Bm + (size_t)(n0 + q0r) * KPRIME + k0 + q0c * 8);
        cp_async16(sb + q1r * KPAD + q1c * 16, Bm + (size_t)(n0 + q1r) * KPRIME + k0 + q1c * 8);
    };

    // warp layout: 2 (m) x 4 (n); warp tile 64x32
    const int wm = (wid >> 2) * 64;
    const int wn = (wid & 3) * 32;
    // ldmatrix lane addressing
    const int mi   = lane >> 3, lr = lane & 7;
    const int rowA = wm + (mi & 1) * 8 + lr;
    const int rowB = wn + (mi & 1) * 8 + lr;
    const int colB = (mi >> 1) * 16;

    float acc[4][4][4];
    #pragma unroll
    for (int a = 0; a < 4; a++)
        #pragma unroll
        for (int b = 0; b < 4; b++)
            #pragma unroll
            for (int c = 0; c < 4; c++) acc[a][b][c] = 0.f;

    load_stage(0, 0);  cp_commit();
    load_stage(1, 32); cp_commit();

    for (int it = 0; it < ITERS; it++) {
        cp_wait<1>();
        __syncthreads();
        const int stg = it % NSTG;
        if (it + 2 < ITERS) load_stage((it + 2) % NSTG, (it + 2) * 32);
        cp_commit();

        const uint32_t sA = sbase + stg * STG_SZ;
        const uint32_t sB = sA + STG_A;
        #pragma unroll
        for (int kh = 0; kh < 2; kh++) {
            uint32_t af[4][4], bf2[2][4];
            #pragma unroll
            for (int mt = 0; mt < 4; mt++)
                ldsm_x4(af[mt], sA + (uint32_t)(rowA + mt * 16) * KPAD + kh * 32 + colB);
            #pragma unroll
            for (int ntp = 0; ntp < 2; ntp++)
                ldsm_x4(bf2[ntp], sB + (uint32_t)(rowB + ntp * 16) * KPAD + kh * 32 + colB);
            #pragma unroll
            for (int mt = 0; mt < 4; mt++)
                #pragma unroll
                for (int nt = 0; nt < 4; nt++)
                    mma_bf16(acc[mt][nt], af[mt],
                             bf2[nt >> 1][nt & 1], bf2[nt >> 1][2 + (nt & 1)]);
        }
        __syncthreads();
    }

    // epilogue
    const int er = m0 + wm + (lane >> 2);
    const int ec = n0 + wn + (lane & 3) * 2;
    #pragma unroll
    for (int mt = 0; mt < 4; mt++) {
        #pragma unroll
        for (int half = 0; half < 2; half++) {
            const int row = er + mt * 16 + half * 8;
            #pragma unroll
            for (int nt = 0; nt < 4; nt++) {
                const int col = ec + nt * 8;
                float v0 = acc[mt][nt][half * 2 + 0];
                float v1 = acc[mt][nt][half * 2 + 1];
                if (MODE == 1) {
                    float* dst = (row < 512) ? (g_Y1 + (size_t)row * NT_ + col)
                                             : (g_Hs + (size_t)(row - 512) * NT_ + col);
                    *(float2*)dst = make_float2(v0, v1);
                } else {
                    const float bv = bias[row];
                    const float2 h = *(const float2*)(g_Hs + (size_t)row * NT_ + col);
                    *(float2*)(g_Hf + (size_t)row * NT_ + col) =
                        make_float2(v0 + bv + h.x, v1 + bv + h.y);
                }
            }
        }
    }
}

// ---------------- BatchNorm stats over bt per channel o ----------------------
__global__ __launch_bounds__(256) void bn_stats(
    const float* __restrict__ g1, const float* __restrict__ b1)
{
    const int o = blockIdx.x, tid = threadIdx.x;
    __shared__ float red[32];
    const float* p = g_Y1 + (size_t)o * NT_;
    float s = 0.f, s2 = 0.f;
    for (int j = tid; j < NT_; j += 256) { float v = p[j]; s += v; s2 += v * v; }
    s  = blockReduceSum(s,  red);
    s2 = blockReduceSum(s2, red);
    if (tid == 0) {
        float mu  = s  * (1.f / 8192.f);
        float var = s2 * (1.f / 8192.f) - mu * mu;
        float sc  = rsqrtf(var + 1e-5f) * g1[o];
        g_scale[o] = sc;
        g_shift[o] = fmaf(-mu, sc, b1[o]);
    }
}

// ---------------- LayerNorm(channel) + L2 normalize -> Lh [d][bt] ------------
__global__ __launch_bounds__(256) void ln_local(
    const float* __restrict__ lng, const float* __restrict__ lnb)
{
    const int q0 = blockIdx.x * 32;
    const int tx = threadIdx.x & 31, ty = threadIdx.x >> 5;
    const float* base = g_Hf + q0 + tx;
    __shared__ float r1[8][33], r2[8][33];
    __shared__ float mu_s[32], rs_s[32], rn_s[32];

    float s = 0.f, s2 = 0.f;
    for (int p = ty; p < MI_; p += 8) {
        float v = base[(size_t)p * NT_];
        s += v; s2 += v * v;
    }
    r1[ty][tx] = s; r2[ty][tx] = s2;
    __syncthreads();
    if (ty == 0) {
        float a = 0.f, c = 0.f;
        #pragma unroll
        for (int i = 0; i < 8; i++) { a += r1[i][tx]; c += r2[i][tx]; }
        float mu  = a * (1.f / 512.f);
        float var = c * (1.f / 512.f) - mu * mu;
        mu_s[tx] = mu;
        rs_s[tx] = rsqrtf(var + 1e-5f);
    }
    __syncthreads();
    float mu = mu_s[tx], rs = rs_s[tx];

    float n2 = 0.f;
    for (int p = ty; p < MI_; p += 8) {
        float v = base[(size_t)p * NT_];
        float z = fmaf((v - mu) * rs, lng[p], lnb[p]);
        n2 += z * z;
    }
    __syncthreads();
    r1[ty][tx] = n2;
    __syncthreads();
    if (ty == 0) {
        float a = 0.f;
        #pragma unroll
        for (int i = 0; i < 8; i++) a += r1[i][tx];
        rn_s[tx] = 1.f / sqrtf(a);
    }
    __syncthreads();
    float rn = rn_s[tx];

    float* ob = g_Lh + q0 + tx;
    for (int p = ty; p < MI_; p += 8) {
        float v = base[(size_t)p * NT_];
        float z = fmaf((v - mu) * rs, lng[p], lnb[p]);
        ob[(size_t)p * NT_] = z * rn;
    }
}

// ---------------- Global path (tiny) -----------------------------------------
__global__ __launch_bounds__(256) void g_mlp1(
    const float* __restrict__ gx, const float* __restrict__ gW1,
    const float* __restrict__ gWs)
{
    const int b = blockIdx.x, tid = threadIdx.x;
    __shared__ float xs[CG_];
    if (tid < CG_) xs[tid] = gx[b * CG_ + tid];
    __syncthreads();
    for (int o = tid; o < MI_; o += 256) {
        const float* w1 = gW1 + (size_t)o * CG_;
        const float* ws = gWs + (size_t)o * CG_;
        float a = 0.f, c = 0.f;
        #pragma unroll 4
        for (int k = 0; k < CG_; k++) {
            float xv = xs[k];
            a = fmaf(w1[k], xv, a);
            c = fmaf(ws[k], xv, c);
        }
        g_yg[b * MI_ + o] = a;
        g_hg[b * MI_ + o] = c;
    }
}

__global__ void g_bn(const float* __restrict__ gg1, const float* __restrict__ gb1)
{
    const int o = threadIdx.x;   // 512 threads
    float s = 0.f, s2 = 0.f;
    #pragma unroll
    for (int b = 0; b < B_; b++) {
        float v = g_yg[b * MI_ + o];
        s += v; s2 += v * v;
    }
    float mu  = s  * (1.f / 32.f);
    float var = s2 * (1.f / 32.f) - mu * mu;
    float sc  = rsqrtf(var + 1e-5f) * gg1[o];
    g_gscale[o] = sc;
    g_gshift[o] = fmaf(-mu, sc, gb1[o]);
}

__global__ __launch_bounds__(256) void g_mlp2(
    const float* __restrict__ gW2, const float* __restrict__ gb2)
{
    const int b = blockIdx.x, tid = threadIdx.x;
    __shared__ float a[MI_];
    for (int o = tid; o < MI_; o += 256)
        a[o] = fmaxf(fmaf(g_yg[b * MI_ + o], g_gscale[o], g_gshift[o]), 0.f);
    __syncthreads();
    for (int p = tid; p < MI_; p += 256) {
        const float* w = gW2 + (size_t)p * MI_;
        float acc = 0.f;
        #pragma unroll 4
        for (int k = 0; k < MI_; k++) acc = fmaf(w[k], a[k], acc);
        g_hg[b * MI_ + p] = acc + gb2[p] + g_hg[b * MI_ + p];
    }
}

__global__ __launch_bounds__(256) void g_ln(
    const float* __restrict__ glng, const float* __restrict__ glnb)
{
    const int b = blockIdx.x, tid = threadIdx.x;
    __shared__ float red[32];
    __shared__ float sh;
    float v0 = g_hg[b * MI_ + tid];
    float v1 = g_hg[b * MI_ + tid + 256];
    float s = blockReduceSum(v0 + v1, red);
    if (tid == 0) sh = s * (1.f / 512.f);
    __syncthreads();
    float mu = sh;
    float d0 = v0 - mu, d1 = v1 - mu;
    float q = blockReduceSum(d0 * d0 + d1 * d1, red);
    if (tid == 0) sh = rsqrtf(q * (1.f / 512.f) + 1e-5f);
    __syncthreads();
    float rs = sh;
    float z0 = fmaf(d0 * rs, glng[tid],       glnb[tid]);
    float z1 = fmaf(d1 * rs, glng[tid + 256], glnb[tid + 256]);
    float n2 = blockReduceSum(z0 * z0 + z1 * z1, red);
    if (tid == 0) sh = 1.f / sqrtf(n2);
    __syncthreads();
    float rn = sh;
    g_Ghat[b * MI_ + tid]       = z0 * rn;
    g_Ghat[b * MI_ + tid + 256] = z1 * rn;
}

// ---------------- u[n][bt] = dot(Ghat[n], Lh[:,bt]) --------------------------
__global__ __launch_bounds__(256) void gemm_uall()
{
    const int q0 = blockIdx.x * 64;  // 128 blocks
    __shared__ float sG[32][36];
    __shared__ float sL[32][68];
    const int tid = threadIdx.x;
    const int ty = tid >> 4, tx = tid & 15;
    float acc[2][4] = {};

    for (int d0 = 0; d0 < MI_; d0 += 32) {
        __syncthreads();
        {
            int n = tid >> 3, k4 = (tid & 7) * 4;
            *(float4*)&sG[n][k4] = *(const float4*)&g_Ghat[n * MI_ + d0 + k4];
        }
        {
            int k = tid >> 4, c4 = (tid & 15) * 4;
            *(float4*)&sL[k][c4] =
                *(const float4*)&g_Lh[(size_t)(d0 + k) * NT_ + q0 + c4];
            *(float4*)&sL[k + 16][c4] =
                *(const float4*)&g_Lh[(size_t)(d0 + k + 16) * NT_ + q0 + c4];
        }
        __syncthreads();
        #pragma unroll
        for (int kk = 0; kk < 32; kk++) {
            float a0 = sG[ty * 2][kk], a1 = sG[ty * 2 + 1][kk];
            float4 bv = *(const float4*)&sL[kk][tx * 4];
            acc[0][0] = fmaf(a0, bv.x, acc[0][0]);
            acc[0][1] = fmaf(a0, bv.y, acc[0][1]);
            acc[0][2] = fmaf(a0, bv.z, acc[0][2]);
            acc[0][3] = fmaf(a0, bv.w, acc[0][3]);
            acc[1][0] = fmaf(a1, bv.x, acc[1][0]);
            acc[1][1] = fmaf(a1, bv.y, acc[1][1]);
            acc[1][2] = fmaf(a1, bv.z, acc[1][2]);
            acc[1][3] = fmaf(a1, bv.w, acc[1][3]);
        }
    }
    #pragma unroll
    for (int i = 0; i < 2; i++) {
        *(float4*)&g_uall[(size_t)(ty * 2 + i) * NT_ + q0 + tx * 4] =
            make_float4(acc[i][0], acc[i][1], acc[i][2], acc[i][3]);
    }
}

// ---------------- loss --------------------------------------------------------
__global__ void zero_out(float* out) { *out = 0.f; }

__global__ __launch_bounds__(256) void loss_kernel(float* __restrict__ out)
{
    const int n = blockIdx.x, tid = threadIdx.x;
    const float* u = g_uall + (size_t)n * NT_;
    __shared__ float red[32];
    __shared__ float sh;

    float m = -1e30f;
    for (int j = tid; j < NT_; j += 256)
        if ((j >> 8) != n) m = fmaxf(m, u[j]);
    #pragma unroll
    for (int o = 16; o; o >>= 1) m = fmaxf(m, __shfl_xor_sync(0xffffffffu, m, o));
    int lane = tid & 31, wid = tid >> 5;
    if (lane == 0) red[wid] = m;
    __syncthreads();
    if (tid < 32) {
        float v = (tid < 8) ? red[tid] : -1e30f;
        #pragma unroll
        for (int o = 4; o; o >>= 1) v = fmaxf(v, __shfl_xor_sync(0xffffffffu, v, o));
        if (tid == 0) sh = v;
    }
    __syncthreads();
    float M = sh;

    float s = 0.f;
    for (int j = tid; j < NT_; j += 256)
        if ((j >> 8) != n) s += expf(u[j] - M);
    s = blockReduceSum(s, red);
    if (tid == 0) sh = M + logf(s);
    __syncthreads();
    float A = sh;

    float p  = u[n * T_ + tid] / 0.07f;
    float mx = fmaxf(p, A);
    float c  = p - (mx + logf(expf(p - mx) + expf(A - mx)));
    c = blockReduceSum(c, red);
    if (tid == 0) atomicAdd(out, -c / (float)NT_);
}

// ---------------- launch ------------------------------------------------------
extern "C" void kernel_launch(void* const* d_in, const int* in_sizes, int n_in,
                              void* d_out, int out_size)
{
    const float* x    = (const float*)d_in[0];
    const float* gx   = (const float*)d_in[1];
    const float* lW1  = (const float*)d_in[2];
    const float* lg1  = (const float*)d_in[3];
    const float* lb1  = (const float*)d_in[4];
    const float* lW2  = (const float*)d_in[5];
    const float* lb2  = (const float*)d_in[6];
    const float* lWs  = (const float*)d_in[7];
    const float* llng = (const float*)d_in[8];
    const float* llnb = (const float*)d_in[9];
    const float* gW1  = (const float*)d_in[10];
    const float* gg1  = (const float*)d_in[11];
    const float* gb1  = (const float*)d_in[12];
    const float* gW2  = (const float*)d_in[13];
    const float* gb2  = (const float*)d_in[14];
    const float* gWs  = (const float*)d_in[15];
    const float* glng = (const float*)d_in[16];
    const float* glnb = (const float*)d_in[17];
    float* out = (float*)d_out;

    cudaFuncSetAttribute(gemm_mma<1>, cudaFuncAttributeMaxDynamicSharedMemorySize, GEMM_SMEM);
    cudaFuncSetAttribute(gemm_mma<2>, cudaFuncAttributeMaxDynamicSharedMemorySize, GEMM_SMEM);

    zero_out<<<1, 1>>>(out);

    // operand prep
    split_wA<<<1024, 256>>>(lW1, lWs);
    split_x<<<dim3(4, 24, 32), 256>>>(x);

    // GEMM1: [W1;Ws] x -> Y1, Hs   (HMMA, split-bf16)
    gemm_mma<1><<<dim3(64, 8), 256, GEMM_SMEM>>>(nullptr);

    bn_stats<<<512, 256>>>(lg1, lb1);
    split_y<<<dim3(128, 8), 256>>>();
    split_w2<<<512, 256>>>(lW2);

    // GEMM2: W2 relu(bn(Y1)) + b2 + Hs -> Hf
    gemm_mma<2><<<dim3(64, 4), 256, GEMM_SMEM>>>(lb2);

    ln_local<<<256, 256>>>(llng, llnb);

    // global path
    g_mlp1<<<32, 256>>>(gx, gW1, gWs);
    g_bn<<<1, 512>>>(gg1, gb1);
    g_mlp2<<<32, 256>>>(gW2, gb2);
    g_ln<<<32, 256>>>(glng, glnb);

    // infonce
    gemm_uall<<<128, 256>>>();
    loss_kernel<<<32, 256>>>(out);
}

// round 6
// speedup vs baseline: 1.3428x; 1.0140x over previous
#include <cuda_runtime.h>
#include <cuda_bf16.h>
#include <math.h>
#include <cstdint>

// Problem dims (fixed by dataset)
constexpr int B_  = 32;
constexpr int CL_ = 1536;
constexpr int T_  = 256;
constexpr int MI_ = 512;
constexpr int CG_ = 192;
constexpr int NT_ = B_ * T_;          // 8192

// ---------------- scratch (static __device__ — no allocs allowed) -----------
__device__ __nv_bfloat16 g_Xhi [(size_t)NT_ * CL_];  // x^T hi   [bt][c]
__device__ __nv_bfloat16 g_Xlo [(size_t)NT_ * CL_];  // x^T lo
__device__ __nv_bfloat16 g_Whi [(size_t)1024 * CL_]; // [W1;Ws] hi
__device__ __nv_bfloat16 g_Wlo [(size_t)1024 * CL_];
__device__ __nv_bfloat16 g_X2hi[(size_t)NT_ * MI_];  // relu(bn(Y1))^T hi
__device__ __nv_bfloat16 g_X2lo[(size_t)NT_ * MI_];
__device__ __nv_bfloat16 g_W2hi[(size_t)MI_ * MI_];
__device__ __nv_bfloat16 g_W2lo[(size_t)MI_ * MI_];
__device__ float g_Y1[(size_t)MI_ * NT_];            // conv1 out   [o][bt]
__device__ float g_Hs[(size_t)MI_ * NT_];            // shortcut    [o][bt]
__device__ float g_Hf[(size_t)MI_ * NT_];            // final h     [o][bt]
__device__ float g_Lh[(size_t)MI_ * NT_];            // normalized locals [d][bt]
__device__ float g_scale[MI_], g_shift[MI_];
__device__ float g_yg[B_ * MI_], g_hg[B_ * MI_];
__device__ float g_gscale[MI_], g_gshift[MI_];
__device__ float g_Ghat[B_ * MI_];
__device__ float g_uall[(size_t)B_ * NT_];

// ---------------- small helpers ----------------------------------------------
__device__ __forceinline__ uint32_t smem_u32(const void* p) {
    uint32_t a;
    asm("{ .reg .u64 t; cvta.to.shared.u64 t, %1; cvt.u32.u64 %0, t; }"
        : "=r"(a) : "l"(p));
    return a;
}
__device__ __forceinline__ void cp_async16(uint32_t saddr, const void* gaddr) {
    asm volatile("cp.async.cg.shared.global [%0], [%1], 16;"
                 :: "r"(saddr), "l"(gaddr) : "memory");
}
__device__ __forceinline__ void cp_commit() {
    asm volatile("cp.async.commit_group;" ::: "memory");
}
template<int N>
__device__ __forceinline__ void cp_wait() {
    asm volatile("cp.async.wait_group %0;" :: "n"(N) : "memory");
}
__device__ __forceinline__ void ldsm_x4(uint32_t* r, uint32_t addr) {
    asm volatile("ldmatrix.sync.aligned.m8n8.x4.shared.b16 {%0,%1,%2,%3}, [%4];"
                 : "=r"(r[0]), "=r"(r[1]), "=r"(r[2]), "=r"(r[3]) : "r"(addr));
}
__device__ __forceinline__ void mma_bf16(float* d, const uint32_t* a,
                                         uint32_t b0, uint32_t b1) {
    asm volatile("mma.sync.aligned.m16n8k16.row.col.f32.bf16.bf16.f32 "
                 "{%0,%1,%2,%3}, {%4,%5,%6,%7}, {%8,%9}, {%0,%1,%2,%3};"
                 : "+f"(d[0]), "+f"(d[1]), "+f"(d[2]), "+f"(d[3])
                 : "r"(a[0]), "r"(a[1]), "r"(a[2]), "r"(a[3]), "r"(b0), "r"(b1));
}

__device__ __forceinline__ float blockReduceSum(float v, float* red) {
    __syncthreads();
    #pragma unroll
    for (int o = 16; o; o >>= 1) v += __shfl_xor_sync(0xffffffffu, v, o);
    int lane = threadIdx.x & 31, wid = threadIdx.x >> 5;
    if (lane == 0) red[wid] = v;
    __syncthreads();
    if (threadIdx.x < 32) {
        float t = (threadIdx.x < (blockDim.x >> 5)) ? red[threadIdx.x] : 0.f;
        #pragma unroll
        for (int o = 4; o; o >>= 1) t += __shfl_xor_sync(0xffffffffu, t, o);
        if (threadIdx.x == 0) red[0] = t;
    }
    __syncthreads();
    return red[0];
}

// ---------------- operand prep ------------------------------------------------
// x [b][c][t] fp32 -> Xhi/Xlo [bt][c] bf16 (transpose + split)
__global__ __launch_bounds__(256) void split_x(const float* __restrict__ x)
{
    __shared__ float tile[64][65];
    const int b = blockIdx.z, c0 = blockIdx.y * 64, t0 = blockIdx.x * 64;
    const int tid = threadIdx.x;
    #pragma unroll
    for (int it = 0; it < 16; it++) {
        int i = it * 256 + tid, c = i >> 6, t = i & 63;
        tile[c][t] = x[((size_t)b * CL_ + c0 + c) * T_ + t0 + t];
    }
    __syncthreads();
    #pragma unroll
    for (int it = 0; it < 16; it++) {
        int i = it * 256 + tid, r = i >> 6, col = i & 63;
        float v = tile[col][r];
        __nv_bfloat16 hi = __float2bfloat16(v);
        __nv_bfloat16 lo = __float2bfloat16(v - __bfloat162float(hi));
        size_t row = (size_t)(b * T_ + t0 + r) * CL_;
        g_Xhi[row + c0 + col] = hi;
        g_Xlo[row + c0 + col] = lo;
    }
}

// W1, Ws -> Whi/Wlo [1024][c]
__global__ __launch_bounds__(256) void split_wA(const float* __restrict__ W1,
                                                const float* __restrict__ Ws)
{
    const int r = blockIdx.x;
    for (int c = threadIdx.x; c < CL_; c += 256) {
        float v = (r < 512) ? W1[(size_t)r * CL_ + c] : Ws[(size_t)(r - 512) * CL_ + c];
        __nv_bfloat16 hi = __float2bfloat16(v);
        __nv_bfloat16 lo = __float2bfloat16(v - __bfloat162float(hi));
        g_Whi[(size_t)r * CL_ + c] = hi;
        g_Wlo[(size_t)r * CL_ + c] = lo;
    }
}

// relu(bn(Y1)) [o][bt] -> X2hi/lo [bt][o]
__global__ __launch_bounds__(256) void split_y()
{
    __shared__ float tile[64][65];
    const int o0 = blockIdx.y * 64, q0 = blockIdx.x * 64;
    const int tid = threadIdx.x;
    #pragma unroll
    for (int it = 0; it < 16; it++) {
        int i = it * 256 + tid, c = i >> 6, t = i & 63;
        float v = g_Y1[(size_t)(o0 + c) * NT_ + q0 + t];
        tile[c][t] = fmaxf(fmaf(v, g_scale[o0 + c], g_shift[o0 + c]), 0.f);
    }
    __syncthreads();
    #pragma unroll
    for (int it = 0; it < 16; it++) {
        int i = it * 256 + tid, r = i >> 6, col = i & 63;
        float v = tile[col][r];
        __nv_bfloat16 hi = __float2bfloat16(v);
        __nv_bfloat16 lo = __float2bfloat16(v - __bfloat162float(hi));
        size_t row = (size_t)(q0 + r) * MI_;
        g_X2hi[row + o0 + col] = hi;
        g_X2lo[row + o0 + col] = lo;
    }
}

// W2 -> W2hi/lo
__global__ __launch_bounds__(256) void split_w2(const float* __restrict__ W2)
{
    const int r = blockIdx.x;
    for (int c = threadIdx.x; c < MI_; c += 256) {
        float v = W2[(size_t)r * MI_ + c];
        __nv_bfloat16 hi = __float2bfloat16(v);
        __nv_bfloat16 lo = __float2bfloat16(v - __bfloat162float(hi));
        g_W2hi[(size_t)r * MI_ + c] = hi;
        g_W2lo[(size_t)r * MI_ + c] = lo;
    }
}

// ---------------- HMMA GEMM (mma.sync bf16, fp32 accum, split-bf16 3-term) ----
// D[m][n] = sum_k' A'[m][k'] * B'[n][k']  with A'=[Whi,Wlo,Whi], B'=[Xhi,Xhi,Xlo]
// CTA tile 128(m) x 256(n), BK=32, 256 threads, 8 warps (warp tile 64x64), 4-stage.
constexpr int KPAD   = 80;                  // bytes per 32-bf16 row (64B + 16B pad)
constexpr int A_BYT  = 128 * KPAD;          // 10240
constexpr int STG_SZ = A_BYT + 256 * KPAD;  // 30720 per stage
constexpr int NSTG   = 4;
constexpr int GEMM_SMEM = NSTG * STG_SZ;    // 122880

template<int MODE>
__global__ __launch_bounds__(256, 1) void gemm_mma(const float* __restrict__ bias)
{
    constexpr int REG   = (MODE == 1) ? CL_ : MI_;    // region k-size
    constexpr int ITERS = 3 * REG / 32;
    const __nv_bfloat16* __restrict__ Ahi = (MODE == 1) ? g_Whi  : g_W2hi;
    const __nv_bfloat16* __restrict__ Alo = (MODE == 1) ? g_Wlo  : g_W2lo;
    const __nv_bfloat16* __restrict__ Bhi = (MODE == 1) ? g_Xhi  : g_X2hi;
    const __nv_bfloat16* __restrict__ Blo = (MODE == 1) ? g_Xlo  : g_X2lo;

    extern __shared__ char smem[];
    const uint32_t sbase = smem_u32(smem);
    const int tid = threadIdx.x, wid = tid >> 5, lane = tid & 31;
    const int n0 = blockIdx.x * 256;
    const int m0 = blockIdx.y * 128;

    const int lr4 = tid >> 2, lc4 = (tid & 3);   // row, 16B-chunk within 128B

    auto load_stage = [&](int stg, int it) {
        const int k0 = it * 32;
        const int r  = k0 / REG;
        const int ko = k0 - r * REG;
        const __nv_bfloat16* Ab = ((r == 1) ? Alo : Ahi) + ko;
        const __nv_bfloat16* Bb = ((r == 2) ? Blo : Bhi) + ko;
        const uint32_t sa = sbase + stg * STG_SZ;
        const uint32_t sb = sa + A_BYT;
        cp_async16(sa + lr4 * KPAD + lc4 * 16,
                   Ab + (size_t)(m0 + lr4) * REG + lc4 * 8);
        cp_async16(sa + (64 + lr4) * KPAD + lc4 * 16,
                   Ab + (size_t)(m0 + 64 + lr4) * REG + lc4 * 8);
        #pragma unroll
        for (int j = 0; j < 4; j++)
            cp_async16(sb + (j * 64 + lr4) * KPAD + lc4 * 16,
                       Bb + (size_t)(n0 + j * 64 + lr4) * REG + lc4 * 8);
    };

    // warp layout: 2 (m) x 4 (n); warp tile 64x64
    const int wm = (wid >> 2) * 64;
    const int wn = (wid & 3) * 64;
    const int mi = lane >> 3, lr = lane & 7;
    const int rowA = wm + (mi & 1) * 8 + lr;
    const int rowB = wn + (mi & 1) * 8 + lr;
    const int colK = (mi >> 1) * 16;

    float acc[4][8][4];
    #pragma unroll
    for (int a = 0; a < 4; a++)
        #pragma unroll
        for (int b = 0; b < 8; b++)
            #pragma unroll
            for (int c = 0; c < 4; c++) acc[a][b][c] = 0.f;

    load_stage(0, 0); cp_commit();
    load_stage(1, 1); cp_commit();
    load_stage(2, 2); cp_commit();

    for (int it = 0; it < ITERS; it++) {
        cp_wait<2>();
        __syncthreads();
        if (it + 3 < ITERS) load_stage((it + 3) & 3, it + 3);
        cp_commit();

        const uint32_t sA = sbase + (it & 3) * STG_SZ;
        const uint32_t sB = sA + A_BYT;
        #pragma unroll
        for (int kh = 0; kh < 2; kh++) {
            uint32_t af[4][4], bf[4][4];
            #pragma unroll
            for (int mt = 0; mt < 4; mt++)
                ldsm_x4(af[mt], sA + (uint32_t)(rowA + mt * 16) * KPAD + kh * 32 + colK);
            #pragma unroll
            for (int ntp = 0; ntp < 4; ntp++)
                ldsm_x4(bf[ntp], sB + (uint32_t)(rowB + ntp * 16) * KPAD + kh * 32 + colK);
            #pragma unroll
            for (int mt = 0; mt < 4; mt++)
                #pragma unroll
                for (int nt = 0; nt < 8; nt++)
                    mma_bf16(acc[mt][nt], af[mt],
                             bf[nt >> 1][nt & 1], bf[nt >> 1][2 + (nt & 1)]);
        }
    }

    // epilogue
    const int er = m0 + wm + (lane >> 2);
    const int ec = n0 + wn + (lane & 3) * 2;
    #pragma unroll
    for (int mt = 0; mt < 4; mt++) {
        #pragma unroll
        for (int half = 0; half < 2; half++) {
            const int row = er + mt * 16 + half * 8;
            #pragma unroll
            for (int nt = 0; nt < 8; nt++) {
                const int col = ec + nt * 8;
                float v0 = acc[mt][nt][half * 2 + 0];
                float v1 = acc[mt][nt][half * 2 + 1];
                if (MODE == 1) {
                    float* dst = (row < 512) ? (g_Y1 + (size_t)row * NT_ + col)
                                             : (g_Hs + (size_t)(row - 512) * NT_ + col);
                    *(float2*)dst = make_float2(v0, v1);
                } else {
                    const float bv = bias[row];
                    const float2 h = *(const float2*)(g_Hs + (size_t)row * NT_ + col);
                    *(float2*)(g_Hf + (size_t)row * NT_ + col) =
                        make_float2(v0 + bv + h.x, v1 + bv + h.y);
                }
            }
        }
    }
}

// ---------------- BatchNorm stats over bt per channel o ----------------------
__global__ __launch_bounds__(256) void bn_stats(
    const float* __restrict__ g1, const float* __restrict__ b1)
{
    const int o = blockIdx.x, tid = threadIdx.x;
    __shared__ float red[32];
    const float* p = g_Y1 + (size_t)o * NT_;
    float s = 0.f, s2 = 0.f;
    for (int j = tid; j < NT_; j += 256) { float v = p[j]; s += v; s2 += v * v; }
    s  = blockReduceSum(s,  red);
    s2 = blockReduceSum(s2, red);
    if (tid == 0) {
        float mu  = s  * (1.f / 8192.f);
        float var = s2 * (1.f / 8192.f) - mu * mu;
        float sc  = rsqrtf(var + 1e-5f) * g1[o];
        g_scale[o] = sc;
        g_shift[o] = fmaf(-mu, sc, b1[o]);
    }
}

// ---------------- LayerNorm(channel) + L2 normalize -> Lh [d][bt] ------------
__global__ __launch_bounds__(256) void ln_local(
    const float* __restrict__ lng, const float* __restrict__ lnb)
{
    const int q0 = blockIdx.x * 32;
    const int tx = threadIdx.x & 31, ty = threadIdx.x >> 5;
    const float* base = g_Hf + q0 + tx;
    __shared__ float r1[8][33], r2[8][33];
    __shared__ float mu_s[32], rs_s[32], rn_s[32];

    float s = 0.f, s2 = 0.f;
    for (int p = ty; p < MI_; p += 8) {
        float v = base[(size_t)p * NT_];
        s += v; s2 += v * v;
    }
    r1[ty][tx] = s; r2[ty][tx] = s2;
    __syncthreads();
    if (ty == 0) {
        float a = 0.f, c = 0.f;
        #pragma unroll
        for (int i = 0; i < 8; i++) { a += r1[i][tx]; c += r2[i][tx]; }
        float mu  = a * (1.f / 512.f);
        float var = c * (1.f / 512.f) - mu * mu;
        mu_s[tx] = mu;
        rs_s[tx] = rsqrtf(var + 1e-5f);
    }
    __syncthreads();
    float mu = mu_s[tx], rs = rs_s[tx];

    float n2 = 0.f;
    for (int p = ty; p < MI_; p += 8) {
        float v = base[(size_t)p * NT_];
        float z = fmaf((v - mu) * rs, lng[p], lnb[p]);
        n2 += z * z;
    }
    __syncthreads();
    r1[ty][tx] = n2;
    __syncthreads();
    if (ty == 0) {
        float a = 0.f;
        #pragma unroll
        for (int i = 0; i < 8; i++) a += r1[i][tx];
        rn_s[tx] = 1.f / sqrtf(a);
    }
    __syncthreads();
    float rn = rn_s[tx];

    float* ob = g_Lh + q0 + tx;
    for (int p = ty; p < MI_; p += 8) {
        float v = base[(size_t)p * NT_];
        float z = fmaf((v - mu) * rs, lng[p], lnb[p]);
        ob[(size_t)p * NT_] = z * rn;
    }
}

// ---------------- Global path (tiny) -----------------------------------------
__global__ __launch_bounds__(256) void g_mlp1(
    const float* __restrict__ gx, const float* __restrict__ gW1,
    const float* __restrict__ gWs)
{
    const int b = blockIdx.x, tid = threadIdx.x;
    __shared__ float xs[CG_];
    if (tid < CG_) xs[tid] = gx[b * CG_ + tid];
    __syncthreads();
    for (int o = tid; o < MI_; o += 256) {
        const float* w1 = gW1 + (size_t)o * CG_;
        const float* ws = gWs + (size_t)o * CG_;
        float a = 0.f, c = 0.f;
        #pragma unroll 4
        for (int k = 0; k < CG_; k++) {
            float xv = xs[k];
            a = fmaf(w1[k], xv, a);
            c = fmaf(ws[k], xv, c);
        }
        g_yg[b * MI_ + o] = a;
        g_hg[b * MI_ + o] = c;
    }
}

__global__ void g_bn(const float* __restrict__ gg1, const float* __restrict__ gb1)
{
    const int o = threadIdx.x;   // 512 threads
    float s = 0.f, s2 = 0.f;
    #pragma unroll
    for (int b = 0; b < B_; b++) {
        float v = g_yg[b * MI_ + o];
        s += v; s2 += v * v;
    }
    float mu  = s  * (1.f / 32.f);
    float var = s2 * (1.f / 32.f) - mu * mu;
    float sc  = rsqrtf(var + 1e-5f) * gg1[o];
    g_gscale[o] = sc;
    g_gshift[o] = fmaf(-mu, sc, gb1[o]);
}

__global__ __launch_bounds__(256) void g_mlp2(
    const float* __restrict__ gW2, const float* __restrict__ gb2)
{
    const int b = blockIdx.x, tid = threadIdx.x;
    __shared__ float a[MI_];
    for (int o = tid; o < MI_; o += 256)
        a[o] = fmaxf(fmaf(g_yg[b * MI_ + o], g_gscale[o], g_gshift[o]), 0.f);
    __syncthreads();
    for (int p = tid; p < MI_; p += 256) {
        const float* w = gW2 + (size_t)p * MI_;
        float acc = 0.f;
        #pragma unroll 4
        for (int k = 0; k < MI_; k++) acc = fmaf(w[k], a[k], acc);
        g_hg[b * MI_ + p] = acc + gb2[p] + g_hg[b * MI_ + p];
    }
}

__global__ __launch_bounds__(256) void g_ln(
    const float* __restrict__ glng, const float* __restrict__ glnb)
{
    const int b = blockIdx.x, tid = threadIdx.x;
    __shared__ float red[32];
    __shared__ float sh;
    float v0 = g_hg[b * MI_ + tid];
    float v1 = g_hg[b * MI_ + tid + 256];
    float s = blockReduceSum(v0 + v1, red);
    if (tid == 0) sh = s * (1.f / 512.f);
    __syncthreads();
    float mu = sh;
    float d0 = v0 - mu, d1 = v1 - mu;
    float q = blockReduceSum(d0 * d0 + d1 * d1, red);
    if (tid == 0) sh = rsqrtf(q * (1.f / 512.f) + 1e-5f);
    __syncthreads();
    float rs = sh;
    float z0 = fmaf(d0 * rs, glng[tid],       glnb[tid]);
    float z1 = fmaf(d1 * rs, glng[tid + 256], glnb[tid + 256]);
    float n2 = blockReduceSum(z0 * z0 + z1 * z1, red);
    if (tid == 0) sh = 1.f / sqrtf(n2);
    __syncthreads();
    float rn = sh;
    g_Ghat[b * MI_ + tid]       = z0 * rn;
    g_Ghat[b * MI_ + tid + 256] = z1 * rn;
}

// ---------------- u[n][bt] = dot(Ghat[n], Lh[:,bt]) --------------------------
__global__ __launch_bounds__(256) void gemm_uall()
{
    const int q0 = blockIdx.x * 64;  // 128 blocks
    __shared__ float sG[32][36];
    __shared__ float sL[32][68];
    const int tid = threadIdx.x;
    const int ty = tid >> 4, tx = tid & 15;
    float acc[2][4] = {};

    for (int d0 = 0; d0 < MI_; d0 += 32) {
        __syncthreads();
        {
            int n = tid >> 3, k4 = (tid & 7) * 4;
            *(float4*)&sG[n][k4] = *(const float4*)&g_Ghat[n * MI_ + d0 + k4];
        }
        {
            int k = tid >> 4, c4 = (tid & 15) * 4;
            *(float4*)&sL[k][c4] =
                *(const float4*)&g_Lh[(size_t)(d0 + k) * NT_ + q0 + c4];
            *(float4*)&sL[k + 16][c4] =
                *(const float4*)&g_Lh[(size_t)(d0 + k + 16) * NT_ + q0 + c4];
        }
        __syncthreads();
        #pragma unroll
        for (int kk = 0; kk < 32; kk++) {
            float a0 = sG[ty * 2][kk], a1 = sG[ty * 2 + 1][kk];
            float4 bv = *(const float4*)&sL[kk][tx * 4];
            acc[0][0] = fmaf(a0, bv.x, acc[0][0]);
            acc[0][1] = fmaf(a0, bv.y, acc[0][1]);
            acc[0][2] = fmaf(a0, bv.z, acc[0][2]);
            acc[0][3] = fmaf(a0, bv.w, acc[0][3]);
            acc[1][0] = fmaf(a1, bv.x, acc[1][0]);
            acc[1][1] = fmaf(a1, bv.y, acc[1][1]);
            acc[1][2] = fmaf(a1, bv.z, acc[1][2]);
            acc[1][3] = fmaf(a1, bv.w, acc[1][3]);
        }
    }
    #pragma unroll
    for (int i = 0; i < 2; i++) {
        *(float4*)&g_uall[(size_t)(ty * 2 + i) * NT_ + q0 + tx * 4] =
            make_float4(acc[i][0], acc[i][1], acc[i][2], acc[i][3]);
    }
}

// ---------------- loss --------------------------------------------------------
__global__ void zero_out(float* out) { *out = 0.f; }

__global__ __launch_bounds__(256) void loss_kernel(float* __restrict__ out)
{
    const int n = blockIdx.x, tid = threadIdx.x;
    const float* u = g_uall + (size_t)n * NT_;
    __shared__ float red[32];
    __shared__ float sh;

    float m = -1e30f;
    for (int j = tid; j < NT_; j += 256)
        if ((j >> 8) != n) m = fmaxf(m, u[j]);
    #pragma unroll
    for (int o = 16; o; o >>= 1) m = fmaxf(m, __shfl_xor_sync(0xffffffffu, m, o));
    int lane = tid & 31, wid = tid >> 5;
    if (lane == 0) red[wid] = m;
    __syncthreads();
    if (tid < 32) {
        float v = (tid < 8) ? red[tid] : -1e30f;
        #pragma unroll
        for (int o = 4; o; o >>= 1) v = fmaxf(v, __shfl_xor_sync(0xffffffffu, v, o));
        if (tid == 0) sh = v;
    }
    __syncthreads();
    float M = sh;

    float s = 0.f;
    for (int j = tid; j < NT_; j += 256)
        if ((j >> 8) != n) s += expf(u[j] - M);
    s = blockReduceSum(s, red);
    if (tid == 0) sh = M + logf(s);
    __syncthreads();
    float A = sh;

    float p  = u[n * T_ + tid] / 0.07f;
    float mx = fmaxf(p, A);
    float c  = p - (mx + logf(expf(p - mx) + expf(A - mx)));
    c = blockReduceSum(c, red);
    if (tid == 0) atomicAdd(out, -c / (float)NT_);
}

// ---------------- launch ------------------------------------------------------
extern "C" void kernel_launch(void* const* d_in, const int* in_sizes, int n_in,
                              void* d_out, int out_size)
{
    const float* x    = (const float*)d_in[0];
    const float* gx   = (const float*)d_in[1];
    const float* lW1  = (const float*)d_in[2];
    const float* lg1  = (const float*)d_in[3];
    const float* lb1  = (const float*)d_in[4];
    const float* lW2  = (const float*)d_in[5];
    const float* lb2  = (const float*)d_in[6];
    const float* lWs  = (const float*)d_in[7];
    const float* llng = (const float*)d_in[8];
    const float* llnb = (const float*)d_in[9];
    const float* gW1  = (const float*)d_in[10];
    const float* gg1  = (const float*)d_in[11];
    const float* gb1  = (const float*)d_in[12];
    const float* gW2  = (const float*)d_in[13];
    const float* gb2  = (const float*)d_in[14];
    const float* gWs  = (const float*)d_in[15];
    const float* glng = (const float*)d_in[16];
    const float* glnb = (const float*)d_in[17];
    float* out = (float*)d_out;

    cudaFuncSetAttribute(gemm_mma<1>, cudaFuncAttributeMaxDynamicSharedMemorySize, GEMM_SMEM);
    cudaFuncSetAttribute(gemm_mma<2>, cudaFuncAttributeMaxDynamicSharedMemorySize, GEMM_SMEM);

    zero_out<<<1, 1>>>(out);

    // operand prep
    split_wA<<<1024, 256>>>(lW1, lWs);
    split_x<<<dim3(4, 24, 32), 256>>>(x);

    // GEMM1: [W1;Ws] x -> Y1, Hs   (HMMA, split-bf16 3-term)
    gemm_mma<1><<<dim3(32, 8), 256, GEMM_SMEM>>>(nullptr);

    bn_stats<<<512, 256>>>(lg1, lb1);
    split_y<<<dim3(128, 8), 256>>>();
    split_w2<<<512, 256>>>(lW2);

    // GEMM2: W2 relu(bn(Y1)) + b2 + Hs -> Hf
    gemm_mma<2><<<dim3(32, 4), 256, GEMM_SMEM>>>(lb2);

    ln_local<<<256, 256>>>(llng, llnb);

    // global path
    g_mlp1<<<32, 256>>>(gx, gW1, gWs);
    g_bn<<<1, 512>>>(gg1, gb1);
    g_mlp2<<<32, 256>>>(gW2, gb2);
    g_ln<<<32, 256>>>(glng, glnb);

    // infonce
    gemm_uall<<<128, 256>>>();
    loss_kernel<<<32, 256>>>(out);
}

// round 9
// speedup vs baseline: 1.7531x; 1.3056x over previous
#include <cuda_runtime.h>
#include <cuda_fp16.h>
#include <math.h>
#include <cstdint>

// Problem dims (fixed by dataset)
constexpr int B_  = 32;
constexpr int CL_ = 1536;
constexpr int T_  = 256;
constexpr int MI_ = 512;
constexpr int CG_ = 192;
constexpr int NT_ = B_ * T_;          // 8192

// ---------------- scratch (static __device__ — no allocs allowed) -----------
__device__ __half g_X1 [(size_t)NT_ * CL_];   // fp16(x)^T      [bt][c]
__device__ __half g_Whi[(size_t)1024 * CL_];  // [W1;Ws] fp16 hi
__device__ __half g_Wlo[(size_t)1024 * CL_];  //          fp16 lo
__device__ __half g_X2 [(size_t)NT_ * MI_];   // fp16(relu(bn(Y1)))^T [bt][o]
__device__ __half g_W2hi[(size_t)MI_ * MI_];
__device__ __half g_W2lo[(size_t)MI_ * MI_];
__device__ float g_Y1[(size_t)MI_ * NT_];     // conv1 out   [o][bt]
__device__ float g_Hs[(size_t)MI_ * NT_];     // shortcut    [o][bt]
__device__ float g_Hf[(size_t)MI_ * NT_];     // final h     [o][bt]
__device__ float g_Lh[(size_t)MI_ * NT_];     // normalized locals [d][bt]
__device__ float g_bnsum[MI_], g_bnsum2[MI_];
__device__ float g_scale[MI_], g_shift[MI_];
__device__ float g_yg[B_ * MI_], g_hg[B_ * MI_];
__device__ float g_gscale[MI_], g_gshift[MI_];
__device__ float g_Ghat[B_ * MI_];
__device__ float g_uall[(size_t)B_ * NT_];

// ---------------- small helpers ----------------------------------------------
__device__ __forceinline__ uint32_t smem_u32(const void* p) {
    uint32_t a;
    asm("{ .reg .u64 t; cvta.to.shared.u64 t, %1; cvt.u32.u64 %0, t; }"
        : "=r"(a) : "l"(p));
    return a;
}
__device__ __forceinline__ void cp_async16(uint32_t saddr, const void* gaddr) {
    asm volatile("cp.async.cg.shared.global [%0], [%1], 16;"
                 :: "r"(saddr), "l"(gaddr) : "memory");
}
__device__ __forceinline__ void cp_commit() {
    asm volatile("cp.async.commit_group;" ::: "memory");
}
template<int N>
__device__ __forceinline__ void cp_wait() {
    asm volatile("cp.async.wait_group %0;" :: "n"(N) : "memory");
}
__device__ __forceinline__ void ldsm_x4(uint32_t* r, uint32_t addr) {
    asm volatile("ldmatrix.sync.aligned.m8n8.x4.shared.b16 {%0,%1,%2,%3}, [%4];"
                 : "=r"(r[0]), "=r"(r[1]), "=r"(r[2]), "=r"(r[3]) : "r"(addr));
}
__device__ __forceinline__ void mma_f16(float* d, const uint32_t* a,
                                        uint32_t b0, uint32_t b1) {
    asm volatile("mma.sync.aligned.m16n8k16.row.col.f32.f16.f16.f32 "
                 "{%0,%1,%2,%3}, {%4,%5,%6,%7}, {%8,%9}, {%0,%1,%2,%3};"
                 : "+f"(d[0]), "+f"(d[1]), "+f"(d[2]), "+f"(d[3])
                 : "r"(a[0]), "r"(a[1]), "r"(a[2]), "r"(a[3]), "r"(b0), "r"(b1));
}

__device__ __forceinline__ float blockReduceSum(float v, float* red) {
    __syncthreads();
    #pragma unroll
    for (int o = 16; o; o >>= 1) v += __shfl_xor_sync(0xffffffffu, v, o);
    int lane = threadIdx.x & 31, wid = threadIdx.x >> 5;
    if (lane == 0) red[wid] = v;
    __syncthreads();
    if (threadIdx.x < 32) {
        float t = (threadIdx.x < (blockDim.x >> 5)) ? red[threadIdx.x] : 0.f;
        #pragma unroll
        for (int o = 4; o; o >>= 1) t += __shfl_xor_sync(0xffffffffu, t, o);
        if (threadIdx.x == 0) red[0] = t;
    }
    __syncthreads();
    return red[0];
}

// ---------------- operand prep ------------------------------------------------
// zero loss + BN accumulators
__global__ void zero_out(float* out) {
    int t = threadIdx.x;
    if (t == 0) *out = 0.f;
    g_bnsum[t] = 0.f; g_bnsum2[t] = 0.f;
}

// x [b][c][t] fp32 -> X1 [bt][c] fp16 (transpose + round)
__global__ __launch_bounds__(256) void split_x(const float* __restrict__ x)
{
    __shared__ float tile[64][65];
    const int b = blockIdx.z, c0 = blockIdx.y * 64, t0 = blockIdx.x * 64;
    const int tid = threadIdx.x;
    #pragma unroll
    for (int it = 0; it < 16; it++) {
        int i = it * 256 + tid, c = i >> 6, t = i & 63;
        tile[c][t] = x[((size_t)b * CL_ + c0 + c) * T_ + t0 + t];
    }
    __syncthreads();
    #pragma unroll
    for (int it = 0; it < 8; it++) {
        int i = it * 256 + tid, r = i >> 5, c2 = (i & 31) * 2;
        float v0 = tile[c2][r], v1 = tile[c2 + 1][r];
        *(__half2*)&g_X1[(size_t)(b * T_ + t0 + r) * CL_ + c0 + c2] =
            __floats2half2_rn(v0, v1);
    }
}

// W1, Ws -> Whi/Wlo [1024][c] fp16 split
__global__ __launch_bounds__(256) void split_wA(const float* __restrict__ W1,
                                                const float* __restrict__ Ws)
{
    const int r = blockIdx.x;
    const float* src = (r < 512) ? (W1 + (size_t)r * CL_) : (Ws + (size_t)(r - 512) * CL_);
    for (int c2 = threadIdx.x * 2; c2 < CL_; c2 += 512) {
        float v0 = src[c2], v1 = src[c2 + 1];
        __half h0 = __float2half_rn(v0), h1 = __float2half_rn(v1);
        __half l0 = __float2half_rn(v0 - __half2float(h0));
        __half l1 = __float2half_rn(v1 - __half2float(h1));
        *(__half2*)&g_Whi[(size_t)r * CL_ + c2] = __halves2half2(h0, h1);
        *(__half2*)&g_Wlo[(size_t)r * CL_ + c2] = __halves2half2(l0, l1);
    }
}

// relu(bn(Y1)) [o][bt] -> X2 [bt][o] fp16
__global__ __launch_bounds__(256) void split_y()
{
    __shared__ float tile[64][65];
    const int o0 = blockIdx.y * 64, q0 = blockIdx.x * 64;
    const int tid = threadIdx.x;
    #pragma unroll
    for (int it = 0; it < 16; it++) {
        int i = it * 256 + tid, c = i >> 6, t = i & 63;
        float v = g_Y1[(size_t)(o0 + c) * NT_ + q0 + t];
        tile[c][t] = fmaxf(fmaf(v, g_scale[o0 + c], g_shift[o0 + c]), 0.f);
    }
    __syncthreads();
    #pragma unroll
    for (int it = 0; it < 8; it++) {
        int i = it * 256 + tid, r = i >> 5, c2 = (i & 31) * 2;
        *(__half2*)&g_X2[(size_t)(q0 + r) * MI_ + o0 + c2] =
            __floats2half2_rn(tile[c2][r], tile[c2 + 1][r]);
    }
}

// W2 -> W2hi/lo fp16 split
__global__ __launch_bounds__(256) void split_w2(const float* __restrict__ W2)
{
    const int r = blockIdx.x;
    const int c2 = threadIdx.x * 2;
    float v0 = W2[(size_t)r * MI_ + c2], v1 = W2[(size_t)r * MI_ + c2 + 1];
    __half h0 = __float2half_rn(v0), h1 = __float2half_rn(v1);
    __half l0 = __float2half_rn(v0 - __half2float(h0));
    __half l1 = __float2half_rn(v1 - __half2float(h1));
    *(__half2*)&g_W2hi[(size_t)r * MI_ + c2] = __halves2half2(h0, h1);
    *(__half2*)&g_W2lo[(size_t)r * MI_ + c2] = __halves2half2(l0, l1);
}

// ---------------- HMMA GEMM (mma.sync fp16, fp32 accum, 2-term W-split) -------
// D[m][n] = sum_k (Whi[m][k]+Wlo[m][k]) * X[n][k]
// CTA tile 128(m) x 256(n), BK=32, 256 threads, 8 warps (warp tile 64x64).
// Per stage: {Whi chunk, Wlo chunk, X chunk} — X loaded once, used by both terms.
constexpr int KPAD   = 80;                  // bytes per 32-half row (64B + 16B pad)
constexpr int AB_BYT = 128 * KPAD;          // 10240 (one 128-row operand block)
constexpr int STG_SZ = 4 * AB_BYT;          // Ahi + Alo + B(256 rows) = 40960
constexpr int NSTG   = 3;
constexpr int GEMM_SMEM = NSTG * STG_SZ;    // 122880

template<int MODE>
__global__ __launch_bounds__(256, 1) void gemm_mma(const float* __restrict__ bias)
{
    constexpr int REG   = (MODE == 1) ? CL_ : MI_;    // k-length
    constexpr int ITERS = REG / 32;
    const __half* __restrict__ Ahi = (MODE == 1) ? g_Whi : g_W2hi;
    const __half* __restrict__ Alo = (MODE == 1) ? g_Wlo : g_W2lo;
    const __half* __restrict__ Bm  = (MODE == 1) ? g_X1  : g_X2;

    extern __shared__ char smem[];
    const uint32_t sbase = smem_u32(smem);
    const int tid = threadIdx.x, wid = tid >> 5, lane = tid & 31;
    const int n0 = blockIdx.x * 256;
    const int m0 = blockIdx.y * 128;

    const int lr4 = tid >> 2, lc4 = tid & 3;   // row 0..63, 16B chunk 0..3

    auto load_stage = [&](int stg, int kc) {
        const int k0 = kc * 32;
        const uint32_t sa = sbase + stg * STG_SZ;
        const uint32_t sl = sa + AB_BYT;
        const uint32_t sb = sa + 2 * AB_BYT;
        cp_async16(sa + lr4 * KPAD + lc4 * 16,
                   Ahi + (size_t)(m0 + lr4) * REG + k0 + lc4 * 8);
        cp_async16(sa + (64 + lr4) * KPAD + lc4 * 16,
                   Ahi + (size_t)(m0 + 64 + lr4) * REG + k0 + lc4 * 8);
        cp_async16(sl + lr4 * KPAD + lc4 * 16,
                   Alo + (size_t)(m0 + lr4) * REG + k0 + lc4 * 8);
        cp_async16(sl + (64 + lr4) * KPAD + lc4 * 16,
                   Alo + (size_t)(m0 + 64 + lr4) * REG + k0 + lc4 * 8);
        #pragma unroll
        for (int j = 0; j < 4; j++)
            cp_async16(sb + (j * 64 + lr4) * KPAD + lc4 * 16,
                       Bm + (size_t)(n0 + j * 64 + lr4) * REG + k0 + lc4 * 8);
    };

    // warp layout: 2 (m) x 4 (n); warp tile 64x64
    const int wm = (wid >> 2) * 64;
    const int wn = (wid & 3) * 64;
    const int mi = lane >> 3, lr = lane & 7;
    const int rowA = wm + (mi & 1) * 8 + lr;
    const int rowB = wn + (mi & 1) * 8 + lr;
    const int colK = (mi >> 1) * 16;

    float acc[4][8][4];
    #pragma unroll
    for (int a = 0; a < 4; a++)
        #pragma unroll
        for (int b = 0; b < 8; b++)
            #pragma unroll
            for (int c = 0; c < 4; c++) acc[a][b][c] = 0.f;

    load_stage(0, 0); cp_commit();
    load_stage(1, 1); cp_commit();

    for (int kc = 0; kc < ITERS; kc++) {
        cp_wait<1>();
        __syncthreads();
        const int stg = kc % NSTG;
        if (kc + 2 < ITERS) load_stage((kc + 2) % NSTG, kc + 2);
        cp_commit();

        const uint32_t sA = sbase + stg * STG_SZ;
        const uint32_t sL = sA + AB_BYT;
        const uint32_t sB = sA + 2 * AB_BYT;
        #pragma unroll
        for (int kh = 0; kh < 2; kh++) {
            uint32_t bf[4][4];
            #pragma unroll
            for (int ntp = 0; ntp < 4; ntp++)
                ldsm_x4(bf[ntp], sB + (uint32_t)(rowB + ntp * 16) * KPAD + kh * 32 + colK);
            {
                uint32_t af[4][4];
                #pragma unroll
                for (int mt = 0; mt < 4; mt++)
                    ldsm_x4(af[mt], sA + (uint32_t)(rowA + mt * 16) * KPAD + kh * 32 + colK);
                #pragma unroll
                for (int mt = 0; mt < 4; mt++)
                    #pragma unroll
                    for (int nt = 0; nt < 8; nt++)
                        mma_f16(acc[mt][nt], af[mt],
                                bf[nt >> 1][nt & 1], bf[nt >> 1][2 + (nt & 1)]);
            }
            {
                uint32_t al[4][4];
                #pragma unroll
                for (int mt = 0; mt < 4; mt++)
                    ldsm_x4(al[mt], sL + (uint32_t)(rowA + mt * 16) * KPAD + kh * 32 + colK);
                #pragma unroll
                for (int mt = 0; mt < 4; mt++)
                    #pragma unroll
                    for (int nt = 0; nt < 8; nt++)
                        mma_f16(acc[mt][nt], al[mt],
                                bf[nt >> 1][nt & 1], bf[nt >> 1][2 + (nt & 1)]);
            }
        }
    }

    // epilogue (+ fused BN partial sums for MODE 1, rows < 512)
    const int er = m0 + wm + (lane >> 2);
    const int ec = n0 + wn + (lane & 3) * 2;
    #pragma unroll
    for (int mt = 0; mt < 4; mt++) {
        #pragma unroll
        for (int half = 0; half < 2; half++) {
            const int row = er + mt * 16 + half * 8;
            float s = 0.f, s2 = 0.f;
            #pragma unroll
            for (int nt = 0; nt < 8; nt++) {
                const int col = ec + nt * 8;
                float v0 = acc[mt][nt][half * 2 + 0];
                float v1 = acc[mt][nt][half * 2 + 1];
                if (MODE == 1) {
                    float* dst = (row < 512) ? (g_Y1 + (size_t)row * NT_ + col)
                                             : (g_Hs + (size_t)(row - 512) * NT_ + col);
                    *(float2*)dst = make_float2(v0, v1);
                    s += v0 + v1; s2 += v0 * v0 + v1 * v1;
                } else {
                    const float bv = bias[row];
                    const float2 h = *(const float2*)(g_Hs + (size_t)row * NT_ + col);
                    *(float2*)(g_Hf + (size_t)row * NT_ + col) =
                        make_float2(v0 + bv + h.x, v1 + bv + h.y);
                }
            }
            if (MODE == 1 && row < 512) {
                s  += __shfl_xor_sync(0xffffffffu, s, 1);
                s  += __shfl_xor_sync(0xffffffffu, s, 2);
                s2 += __shfl_xor_sync(0xffffffffu, s2, 1);
                s2 += __shfl_xor_sync(0xffffffffu, s2, 2);
                if ((lane & 3) == 0) {
                    atomicAdd(&g_bnsum[row], s);
                    atomicAdd(&g_bnsum2[row], s2);
                }
            }
        }
    }
}

// ---------------- BN finalize -------------------------------------------------
__global__ void bn_finalize(const float* __restrict__ g1, const float* __restrict__ b1)
{
    const int o = threadIdx.x;   // 512 threads
    float mu  = g_bnsum[o]  * (1.f / 8192.f);
    float var = g_bnsum2[o] * (1.f / 8192.f) - mu * mu;
    float sc  = rsqrtf(var + 1e-5f) * g1[o];
    g_scale[o] = sc;
    g_shift[o] = fmaf(-mu, sc, b1[o]);
}

// ---------------- LayerNorm(channel) + L2 normalize -> Lh [d][bt] ------------
__global__ __launch_bounds__(256) void ln_local(
    const float* __restrict__ lng, const float* __restrict__ lnb)
{
    const int q0 = blockIdx.x * 32;
    const int tx = threadIdx.x & 31, ty = threadIdx.x >> 5;
    const float* base = g_Hf + q0 + tx;
    __shared__ float r1[8][33], r2[8][33];
    __shared__ float mu_s[32], rs_s[32], rn_s[32];

    float s = 0.f, s2 = 0.f;
    for (int p = ty; p < MI_; p += 8) {
        float v = base[(size_t)p * NT_];
        s += v; s2 += v * v;
    }
    r1[ty][tx] = s; r2[ty][tx] = s2;
    __syncthreads();
    if (ty == 0) {
        float a = 0.f, c = 0.f;
        #pragma unroll
        for (int i = 0; i < 8; i++) { a += r1[i][tx]; c += r2[i][tx]; }
        float mu  = a * (1.f / 512.f);
        float var = c * (1.f / 512.f) - mu * mu;
        mu_s[tx] = mu;
        rs_s[tx] = rsqrtf(var + 1e-5f);
    }
    __syncthreads();
    float mu = mu_s[tx], rs = rs_s[tx];

    float n2 = 0.f;
    for (int p = ty; p < MI_; p += 8) {
        float v = base[(size_t)p * NT_];
        float z = fmaf((v - mu) * rs, lng[p], lnb[p]);
        n2 += z * z;
    }
    __syncthreads();
    r1[ty][tx] = n2;
    __syncthreads();
    if (ty == 0) {
        float a = 0.f;
        #pragma unroll
        for (int i = 0; i < 8; i++) a += r1[i][tx];
        rn_s[tx] = 1.f / sqrtf(a);
    }
    __syncthreads();
    float rn = rn_s[tx];

    float* ob = g_Lh + q0 + tx;
    for (int p = ty; p < MI_; p += 8) {
        float v = base[(size_t)p * NT_];
        float z = fmaf((v - mu) * rs, lng[p], lnb[p]);
        ob[(size_t)p * NT_] = z * rn;
    }
}

// ---------------- Global path (tiny) -----------------------------------------
__global__ __launch_bounds__(256) void g_mlp1(
    const float* __restrict__ gx, const float* __restrict__ gW1,
    const float* __restrict__ gWs)
{
    const int b = blockIdx.x, tid = threadIdx.x;
    __shared__ float xs[CG_];
    if (tid < CG_) xs[tid] = gx[b * CG_ + tid];
    __syncthreads();
    for (int o = tid; o < MI_; o += 256) {
        const float* w1 = gW1 + (size_t)o * CG_;
        const float* ws = gWs + (size_t)o * CG_;
        float a = 0.f, c = 0.f;
        #pragma unroll 4
        for (int k = 0; k < CG_; k++) {
            float xv = xs[k];
            a = fmaf(w1[k], xv, a);
            c = fmaf(ws[k], xv, c);
        }
        g_yg[b * MI_ + o] = a;
        g_hg[b * MI_ + o] = c;
    }
}

__global__ void g_bn(const float* __restrict__ gg1, const float* __restrict__ gb1)
{
    const int o = threadIdx.x;   // 512 threads
    float s = 0.f, s2 = 0.f;
    #pragma unroll
    for (int b = 0; b < B_; b++) {
        float v = g_yg[b * MI_ + o];
        s += v; s2 += v * v;
    }
    float mu  = s  * (1.f / 32.f);
    float var = s2 * (1.f / 32.f) - mu * mu;
    float sc  = rsqrtf(var + 1e-5f) * gg1[o];
    g_gscale[o] = sc;
    g_gshift[o] = fmaf(-mu, sc, gb1[o]);
}

__global__ __launch_bounds__(256) void g_mlp2(
    const float* __restrict__ gW2, const float* __restrict__ gb2)
{
    const int b = blockIdx.x, tid = threadIdx.x;
    __shared__ float a[MI_];
    for (int o = tid; o < MI_; o += 256)
        a[o] = fmaxf(fmaf(g_yg[b * MI_ + o], g_gscale[o], g_gshift[o]), 0.f);
    __syncthreads();
    for (int p = tid; p < MI_; p += 256) {
        const float* w = gW2 + (size_t)p * MI_;
        float acc = 0.f;
        #pragma unroll 4
        for (int k = 0; k < MI_; k++) acc = fmaf(w[k], a[k], acc);
        g_hg[b * MI_ + p] = acc + gb2[p] + g_hg[b * MI_ + p];
    }
}

__global__ __launch_bounds__(256) void g_ln(
    const float* __restrict__ glng, const float* __restrict__ glnb)
{
    const int b = blockIdx.x, tid = threadIdx.x;
    __shared__ float red[32];
    __shared__ float sh;
    float v0 = g_hg[b * MI_ + tid];
    float v1 = g_hg[b * MI_ + tid + 256];
    float s = blockReduceSum(v0 + v1, red);
    if (tid == 0) sh = s * (1.f / 512.f);
    __syncthreads();
    float mu = sh;
    float d0 = v0 - mu, d1 = v1 - mu;
    float q = blockReduceSum(d0 * d0 + d1 * d1, red);
    if (tid == 0) sh = rsqrtf(q * (1.f / 512.f) + 1e-5f);
    __syncthreads();
    float rs = sh;
    float z0 = fmaf(d0 * rs, glng[tid],       glnb[tid]);
    float z1 = fmaf(d1 * rs, glng[tid + 256], glnb[tid + 256]);
    float n2 = blockReduceSum(z0 * z0 + z1 * z1, red);
    if (tid == 0) sh = 1.f / sqrtf(n2);
    __syncthreads();
    float rn = sh;
    g_Ghat[b * MI_ + tid]       = z0 * rn;
    g_Ghat[b * MI_ + tid + 256] = z1 * rn;
}

// ---------------- u[n][bt] = dot(Ghat[n], Lh[:,bt]) --------------------------
__global__ __launch_bounds__(256) void gemm_uall()
{
    const int q0 = blockIdx.x * 64;  // 128 blocks
    __shared__ float sG[32][36];
    __shared__ float sL[32][68];
    const int tid = threadIdx.x;
    const int ty = tid >> 4, tx = tid & 15;
    float acc[2][4] = {};

    for (int d0 = 0; d0 < MI_; d0 += 32) {
        __syncthreads();
        {
            int n = tid >> 3, k4 = (tid & 7) * 4;
            *(float4*)&sG[n][k4] = *(const float4*)&g_Ghat[n * MI_ + d0 + k4];
        }
        {
            int k = tid >> 4, c4 = (tid & 15) * 4;
            *(float4*)&sL[k][c4] =
                *(const float4*)&g_Lh[(size_t)(d0 + k) * NT_ + q0 + c4];
            *(float4*)&sL[k + 16][c4] =
                *(const float4*)&g_Lh[(size_t)(d0 + k + 16) * NT_ + q0 + c4];
        }
        __syncthreads();
        #pragma unroll
        for (int kk = 0; kk < 32; kk++) {
            float a0 = sG[ty * 2][kk], a1 = sG[ty * 2 + 1][kk];
            float4 bv = *(const float4*)&sL[kk][tx * 4];
            acc[0][0] = fmaf(a0, bv.x, acc[0][0]);
            acc[0][1] = fmaf(a0, bv.y, acc[0][1]);
            acc[0][2] = fmaf(a0, bv.z, acc[0][2]);
            acc[0][3] = fmaf(a0, bv.w, acc[0][3]);
            acc[1][0] = fmaf(a1, bv.x, acc[1][0]);
            acc[1][1] = fmaf(a1, bv.y, acc[1][1]);
            acc[1][2] = fmaf(a1, bv.z, acc[1][2]);
            acc[1][3] = fmaf(a1, bv.w, acc[1][3]);
        }
    }
    #pragma unroll
    for (int i = 0; i < 2; i++) {
        *(float4*)&g_uall[(size_t)(ty * 2 + i) * NT_ + q0 + tx * 4] =
            make_float4(acc[i][0], acc[i][1], acc[i][2], acc[i][3]);
    }
}

// ---------------- loss --------------------------------------------------------
__global__ __launch_bounds__(256) void loss_kernel(float* __restrict__ out)
{
    const int n = blockIdx.x, tid = threadIdx.x;
    const float* u = g_uall + (size_t)n * NT_;
    __shared__ float red[32];
    __shared__ float sh;

    float m = -1e30f;
    for (int j = tid; j < NT_; j += 256)
        if ((j >> 8) != n) m = fmaxf(m, u[j]);
    #pragma unroll
    for (int o = 16; o; o >>= 1) m = fmaxf(m, __shfl_xor_sync(0xffffffffu, m, o));
    int lane = tid & 31, wid = tid >> 5;
    if (lane == 0) red[wid] = m;
    __syncthreads();
    if (tid < 32) {
        float v = (tid < 8) ? red[tid] : -1e30f;
        #pragma unroll
        for (int o = 4; o; o >>= 1) v = fmaxf(v, __shfl_xor_sync(0xffffffffu, v, o));
        if (tid == 0) sh = v;
    }
    __syncthreads();
    float M = sh;

    float s = 0.f;
    for (int j = tid; j < NT_; j += 256)
        if ((j >> 8) != n) s += expf(u[j] - M);
    s = blockReduceSum(s, red);
    if (tid == 0) sh = M + logf(s);
    __syncthreads();
    float A = sh;

    float p  = u[n * T_ + tid] / 0.07f;
    float mx = fmaxf(p, A);
    float c  = p - (mx + logf(expf(p - mx) + expf(A - mx)));
    c = blockReduceSum(c, red);
    if (tid == 0) atomicAdd(out, -c / (float)NT_);
}

// ---------------- launch ------------------------------------------------------
extern "C" void kernel_launch(void* const* d_in, const int* in_sizes, int n_in,
                              void* d_out, int out_size)
{
    const float* x    = (const float*)d_in[0];
    const float* gx   = (const float*)d_in[1];
    const float* lW1  = (const float*)d_in[2];
    const float* lg1  = (const float*)d_in[3];
    const float* lb1  = (const float*)d_in[4];
    const float* lW2  = (const float*)d_in[5];
    const float* lb2  = (const float*)d_in[6];
    const float* lWs  = (const float*)d_in[7];
    const float* llng = (const float*)d_in[8];
    const float* llnb = (const float*)d_in[9];
    const float* gW1  = (const float*)d_in[10];
    const float* gg1  = (const float*)d_in[11];
    const float* gb1  = (const float*)d_in[12];
    const float* gW2  = (const float*)d_in[13];
    const float* gb2  = (const float*)d_in[14];
    const float* gWs  = (const float*)d_in[15];
    const float* glng = (const float*)d_in[16];
    const float* glnb = (const float*)d_in[17];
    float* out = (float*)d_out;

    cudaFuncSetAttribute(gemm_mma<1>, cudaFuncAttributeMaxDynamicSharedMemorySize, GEMM_SMEM);
    cudaFuncSetAttribute(gemm_mma<2>, cudaFuncAttributeMaxDynamicSharedMemorySize, GEMM_SMEM);

    zero_out<<<1, 512>>>(out);

    // operand prep
    split_wA<<<1024, 256>>>(lW1, lWs);
    split_w2<<<512, 256>>>(lW2);
    split_x<<<dim3(4, 24, 32), 256>>>(x);

    // GEMM1: [W1;Ws] x -> Y1 (+BN partial sums), Hs
    gemm_mma<1><<<dim3(32, 8), 256, GEMM_SMEM>>>(nullptr);

    bn_finalize<<<1, 512>>>(lg1, lb1);
    split_y<<<dim3(128, 8), 256>>>();

    // GEMM2: W2 relu(bn(Y1)) + b2 + Hs -> Hf
    gemm_mma<2><<<dim3(32, 4), 256, GEMM_SMEM>>>(lb2);

    ln_local<<<256, 256>>>(llng, llnb);

    // global path
    g_mlp1<<<32, 256>>>(gx, gW1, gWs);
    g_bn<<<1, 512>>>(gg1, gb1);
    g_mlp2<<<32, 256>>>(gW2, gb2);
    g_ln<<<32, 256>>>(glng, glnb);

    // infonce
    gemm_uall<<<128, 256>>>();
    loss_kernel<<<32, 256>>>(out);
}

// round 10
// speedup vs baseline: 2.2002x; 1.2550x over previous
#include <cuda_runtime.h>
#include <cuda_fp16.h>
#include <math.h>
#include <cstdint>

// Problem dims (fixed by dataset)
constexpr int B_  = 32;
constexpr int CL_ = 1536;
constexpr int T_  = 256;
constexpr int MI_ = 512;
constexpr int CG_ = 192;
constexpr int NT_ = B_ * T_;          // 8192

// ---------------- scratch (static __device__ — no allocs allowed) -----------
__device__ __half g_X1 [(size_t)NT_ * CL_];   // fp16(x)^T      [bt][c]
__device__ __half g_Wf [(size_t)1024 * CL_];  // [W1;Ws] fp16
__device__ __half g_X2 [(size_t)NT_ * MI_];   // fp16(relu(bn(Y1)))^T [bt][o]
__device__ __half g_W2f[(size_t)MI_ * MI_];   // W2 fp16
__device__ __half g_Y1h[(size_t)MI_ * NT_];   // conv1 out   [o][bt] fp16
__device__ __half g_Hsh[(size_t)MI_ * NT_];   // shortcut    [o][bt] fp16
__device__ __half g_Hfh[(size_t)MI_ * NT_];   // final h     [o][bt] fp16
__device__ float g_bnsum[MI_], g_bnsum2[MI_];
__device__ float g_scale[MI_], g_shift[MI_];
__device__ float g_yg[B_ * MI_], g_hg[B_ * MI_];
__device__ float g_gscale[MI_], g_gshift[MI_];
__device__ float g_Ghat[B_ * MI_];
__device__ float g_uall[(size_t)B_ * NT_];

// ---------------- small helpers ----------------------------------------------
__device__ __forceinline__ uint32_t smem_u32(const void* p) {
    uint32_t a;
    asm("{ .reg .u64 t; cvta.to.shared.u64 t, %1; cvt.u32.u64 %0, t; }"
        : "=r"(a) : "l"(p));
    return a;
}
__device__ __forceinline__ void cp_async16(uint32_t saddr, const void* gaddr) {
    asm volatile("cp.async.cg.shared.global [%0], [%1], 16;"
                 :: "r"(saddr), "l"(gaddr) : "memory");
}
__device__ __forceinline__ void cp_commit() {
    asm volatile("cp.async.commit_group;" ::: "memory");
}
template<int N>
__device__ __forceinline__ void cp_wait() {
    asm volatile("cp.async.wait_group %0;" :: "n"(N) : "memory");
}
__device__ __forceinline__ void ldsm_x4(uint32_t* r, uint32_t addr) {
    asm volatile("ldmatrix.sync.aligned.m8n8.x4.shared.b16 {%0,%1,%2,%3}, [%4];"
                 : "=r"(r[0]), "=r"(r[1]), "=r"(r[2]), "=r"(r[3]) : "r"(addr));
}
__device__ __forceinline__ void mma_f16(float* d, const uint32_t* a,
                                        uint32_t b0, uint32_t b1) {
    asm volatile("mma.sync.aligned.m16n8k16.row.col.f32.f16.f16.f32 "
                 "{%0,%1,%2,%3}, {%4,%5,%6,%7}, {%8,%9}, {%0,%1,%2,%3};"
                 : "+f"(d[0]), "+f"(d[1]), "+f"(d[2]), "+f"(d[3])
                 : "r"(a[0]), "r"(a[1]), "r"(a[2]), "r"(a[3]), "r"(b0), "r"(b1));
}

__device__ __forceinline__ float blockReduceSum(float v, float* red) {
    __syncthreads();
    #pragma unroll
    for (int o = 16; o; o >>= 1) v += __shfl_xor_sync(0xffffffffu, v, o);
    int lane = threadIdx.x & 31, wid = threadIdx.x >> 5;
    if (lane == 0) red[wid] = v;
    __syncthreads();
    if (threadIdx.x < 32) {
        float t = (threadIdx.x < (blockDim.x >> 5)) ? red[threadIdx.x] : 0.f;
        #pragma unroll
        for (int o = 4; o; o >>= 1) t += __shfl_xor_sync(0xffffffffu, t, o);
        if (threadIdx.x == 0) red[0] = t;
    }
    __syncthreads();
    return red[0];
}

// ---------------- operand prep ------------------------------------------------
__global__ void zero_out(float* out) {
    int t = threadIdx.x;
    if (t == 0) *out = 0.f;
    g_bnsum[t] = 0.f; g_bnsum2[t] = 0.f;
}

// weights -> fp16 (W1,Ws rows 0..1023; W2 rows 1024..1535)
__global__ __launch_bounds__(256) void w_to_f16(const float* __restrict__ W1,
                                                const float* __restrict__ Ws,
                                                const float* __restrict__ W2)
{
    const int r = blockIdx.x;
    if (r < 1024) {
        const float* src = (r < 512) ? (W1 + (size_t)r * CL_)
                                     : (Ws + (size_t)(r - 512) * CL_);
        for (int c2 = threadIdx.x * 2; c2 < CL_; c2 += 512)
            *(__half2*)&g_Wf[(size_t)r * CL_ + c2] =
                __floats2half2_rn(src[c2], src[c2 + 1]);
    } else {
        const int rr = r - 1024;
        const int c2 = threadIdx.x * 2;
        *(__half2*)&g_W2f[(size_t)rr * MI_ + c2] =
            __floats2half2_rn(W2[(size_t)rr * MI_ + c2], W2[(size_t)rr * MI_ + c2 + 1]);
    }
}

// x [b][c][t] fp32 -> X1 [bt][c] fp16 (transpose + round)
__global__ __launch_bounds__(256) void split_x(const float* __restrict__ x)
{
    __shared__ float tile[64][65];
    const int b = blockIdx.z, c0 = blockIdx.y * 64, t0 = blockIdx.x * 64;
    const int tid = threadIdx.x;
    #pragma unroll
    for (int it = 0; it < 16; it++) {
        int i = it * 256 + tid, c = i >> 6, t = i & 63;
        tile[c][t] = x[((size_t)b * CL_ + c0 + c) * T_ + t0 + t];
    }
    __syncthreads();
    #pragma unroll
    for (int it = 0; it < 8; it++) {
        int i = it * 256 + tid, r = i >> 5, c2 = (i & 31) * 2;
        *(__half2*)&g_X1[(size_t)(b * T_ + t0 + r) * CL_ + c0 + c2] =
            __floats2half2_rn(tile[c2][r], tile[c2 + 1][r]);
    }
}

// relu(bn(Y1h)) [o][bt] -> X2 [bt][o] fp16
__global__ __launch_bounds__(256) void split_y()
{
    __shared__ float tile[64][65];
    const int o0 = blockIdx.y * 64, q0 = blockIdx.x * 64;
    const int tid = threadIdx.x;
    #pragma unroll
    for (int it = 0; it < 8; it++) {
        int i = it * 256 + tid, c = i >> 5, t2 = (i & 31) * 2;
        __half2 hv = *(const __half2*)&g_Y1h[(size_t)(o0 + c) * NT_ + q0 + t2];
        float2 v = __half22float2(hv);
        float sc = g_scale[o0 + c], sh = g_shift[o0 + c];
        tile[c][t2]     = fmaxf(fmaf(v.x, sc, sh), 0.f);
        tile[c][t2 + 1] = fmaxf(fmaf(v.y, sc, sh), 0.f);
    }
    __syncthreads();
    #pragma unroll
    for (int it = 0; it < 8; it++) {
        int i = it * 256 + tid, r = i >> 5, c2 = (i & 31) * 2;
        *(__half2*)&g_X2[(size_t)(q0 + r) * MI_ + o0 + c2] =
            __floats2half2_rn(tile[c2][r], tile[c2 + 1][r]);
    }
}

// ---------------- HMMA GEMM (mma.sync fp16, fp32 accum, single-term) ----------
// CTA tile 128(m) x 256(n), BK=32, 256 threads, 8 warps (warp tile 64x64).
constexpr int KPAD   = 80;                  // bytes per 32-half row (64B + 16B pad)
constexpr int A_BYT  = 128 * KPAD;          // 10240
constexpr int STG_SZ = A_BYT + 256 * KPAD;  // 30720
constexpr int NSTG   = 3;
constexpr int GEMM_SMEM = NSTG * STG_SZ;    // 92160

template<int MODE>
__global__ __launch_bounds__(256, 1) void gemm_mma(const float* __restrict__ bias)
{
    constexpr int REG   = (MODE == 1) ? CL_ : MI_;
    constexpr int ITERS = REG / 32;
    const __half* __restrict__ A  = (MODE == 1) ? g_Wf : g_W2f;
    const __half* __restrict__ Bm = (MODE == 1) ? g_X1 : g_X2;

    extern __shared__ char smem[];
    const uint32_t sbase = smem_u32(smem);
    const int tid = threadIdx.x, wid = tid >> 5, lane = tid & 31;
    const int n0 = blockIdx.x * 256;
    const int m0 = blockIdx.y * 128;

    const int lr4 = tid >> 2, lc4 = tid & 3;

    auto load_stage = [&](int stg, int kc) {
        const int k0 = kc * 32;
        const uint32_t sa = sbase + stg * STG_SZ;
        const uint32_t sb = sa + A_BYT;
        cp_async16(sa + lr4 * KPAD + lc4 * 16,
                   A + (size_t)(m0 + lr4) * REG + k0 + lc4 * 8);
        cp_async16(sa + (64 + lr4) * KPAD + lc4 * 16,
                   A + (size_t)(m0 + 64 + lr4) * REG + k0 + lc4 * 8);
        #pragma unroll
        for (int j = 0; j < 4; j++)
            cp_async16(sb + (j * 64 + lr4) * KPAD + lc4 * 16,
                       Bm + (size_t)(n0 + j * 64 + lr4) * REG + k0 + lc4 * 8);
    };

    const int wm = (wid >> 2) * 64;
    const int wn = (wid & 3) * 64;
    const int mi = lane >> 3, lr = lane & 7;
    const int rowA = wm + (mi & 1) * 8 + lr;
    const int rowB = wn + (mi & 1) * 8 + lr;
    const int colK = (mi >> 1) * 16;

    float acc[4][8][4];
    #pragma unroll
    for (int a = 0; a < 4; a++)
        #pragma unroll
        for (int b = 0; b < 8; b++)
            #pragma unroll
            for (int c = 0; c < 4; c++) acc[a][b][c] = 0.f;

    load_stage(0, 0); cp_commit();
    load_stage(1, 1); cp_commit();

    for (int kc = 0; kc < ITERS; kc++) {
        cp_wait<1>();
        __syncthreads();
        const int stg = kc % NSTG;
        if (kc + 2 < ITERS) load_stage((kc + 2) % NSTG, kc + 2);
        cp_commit();

        const uint32_t sA = sbase + stg * STG_SZ;
        const uint32_t sB = sA + A_BYT;
        #pragma unroll
        for (int kh = 0; kh < 2; kh++) {
            uint32_t af[4][4], bf[4][4];
            #pragma unroll
            for (int mt = 0; mt < 4; mt++)
                ldsm_x4(af[mt], sA + (uint32_t)(rowA + mt * 16) * KPAD + kh * 32 + colK);
            #pragma unroll
            for (int ntp = 0; ntp < 4; ntp++)
                ldsm_x4(bf[ntp], sB + (uint32_t)(rowB + ntp * 16) * KPAD + kh * 32 + colK);
            #pragma unroll
            for (int mt = 0; mt < 4; mt++)
                #pragma unroll
                for (int nt = 0; nt < 8; nt++)
                    mma_f16(acc[mt][nt], af[mt],
                            bf[nt >> 1][nt & 1], bf[nt >> 1][2 + (nt & 1)]);
        }
    }

    // epilogue (+ fused BN partial sums for MODE 1, rows < 512)
    const int er = m0 + wm + (lane >> 2);
    const int ec = n0 + wn + (lane & 3) * 2;
    #pragma unroll
    for (int mt = 0; mt < 4; mt++) {
        #pragma unroll
        for (int half = 0; half < 2; half++) {
            const int row = er + mt * 16 + half * 8;
            float s = 0.f, s2 = 0.f;
            #pragma unroll
            for (int nt = 0; nt < 8; nt++) {
                const int col = ec + nt * 8;
                float v0 = acc[mt][nt][half * 2 + 0];
                float v1 = acc[mt][nt][half * 2 + 1];
                if (MODE == 1) {
                    __half2* dst = (row < 512)
                        ? (__half2*)(g_Y1h + (size_t)row * NT_ + col)
                        : (__half2*)(g_Hsh + (size_t)(row - 512) * NT_ + col);
                    *dst = __floats2half2_rn(v0, v1);
                    s += v0 + v1; s2 += v0 * v0 + v1 * v1;
                } else {
                    const float bv = bias[row];
                    float2 h = __half22float2(
                        *(const __half2*)(g_Hsh + (size_t)row * NT_ + col));
                    *(__half2*)(g_Hfh + (size_t)row * NT_ + col) =
                        __floats2half2_rn(v0 + bv + h.x, v1 + bv + h.y);
                }
            }
            if (MODE == 1 && row < 512) {
                s  += __shfl_xor_sync(0xffffffffu, s, 1);
                s  += __shfl_xor_sync(0xffffffffu, s, 2);
                s2 += __shfl_xor_sync(0xffffffffu, s2, 1);
                s2 += __shfl_xor_sync(0xffffffffu, s2, 2);
                if ((lane & 3) == 0) {
                    atomicAdd(&g_bnsum[row], s);
                    atomicAdd(&g_bnsum2[row], s2);
                }
            }
        }
    }
}

// ---------------- BN finalize -------------------------------------------------
__global__ void bn_finalize(const float* __restrict__ g1, const float* __restrict__ b1)
{
    const int o = threadIdx.x;   // 512 threads
    float mu  = g_bnsum[o]  * (1.f / 8192.f);
    float var = g_bnsum2[o] * (1.f / 8192.f) - mu * mu;
    float sc  = rsqrtf(var + 1e-5f) * g1[o];
    g_scale[o] = sc;
    g_shift[o] = fmaf(-mu, sc, b1[o]);
}

// ---------------- Global path (tiny) -----------------------------------------
__global__ __launch_bounds__(256) void g_mlp1(
    const float* __restrict__ gx, const float* __restrict__ gW1,
    const float* __restrict__ gWs)
{
    const int b = blockIdx.x, tid = threadIdx.x;
    __shared__ float xs[CG_];
    if (tid < CG_) xs[tid] = gx[b * CG_ + tid];
    __syncthreads();
    for (int o = tid; o < MI_; o += 256) {
        const float* w1 = gW1 + (size_t)o * CG_;
        const float* ws = gWs + (size_t)o * CG_;
        float a = 0.f, c = 0.f;
        #pragma unroll 4
        for (int k = 0; k < CG_; k++) {
            float xv = xs[k];
            a = fmaf(w1[k], xv, a);
            c = fmaf(ws[k], xv, c);
        }
        g_yg[b * MI_ + o] = a;
        g_hg[b * MI_ + o] = c;
    }
}

__global__ void g_bn(const float* __restrict__ gg1, const float* __restrict__ gb1)
{
    const int o = threadIdx.x;   // 512 threads
    float s = 0.f, s2 = 0.f;
    #pragma unroll
    for (int b = 0; b < B_; b++) {
        float v = g_yg[b * MI_ + o];
        s += v; s2 += v * v;
    }
    float mu  = s  * (1.f / 32.f);
    float var = s2 * (1.f / 32.f) - mu * mu;
    float sc  = rsqrtf(var + 1e-5f) * gg1[o];
    g_gscale[o] = sc;
    g_gshift[o] = fmaf(-mu, sc, gb1[o]);
}

__global__ __launch_bounds__(256) void g_mlp2(
    const float* __restrict__ gW2, const float* __restrict__ gb2)
{
    const int b = blockIdx.x, tid = threadIdx.x;
    __shared__ float a[MI_];
    for (int o = tid; o < MI_; o += 256)
        a[o] = fmaxf(fmaf(g_yg[b * MI_ + o], g_gscale[o], g_gshift[o]), 0.f);
    __syncthreads();
    for (int p = tid; p < MI_; p += 256) {
        const float* w = gW2 + (size_t)p * MI_;
        float acc = 0.f;
        #pragma unroll 4
        for (int k = 0; k < MI_; k++) acc = fmaf(w[k], a[k], acc);
        g_hg[b * MI_ + p] = acc + gb2[p] + g_hg[b * MI_ + p];
    }
}

__global__ __launch_bounds__(256) void g_ln(
    const float* __restrict__ glng, const float* __restrict__ glnb)
{
    const int b = blockIdx.x, tid = threadIdx.x;
    __shared__ float red[32];
    __shared__ float sh;
    float v0 = g_hg[b * MI_ + tid];
    float v1 = g_hg[b * MI_ + tid + 256];
    float s = blockReduceSum(v0 + v1, red);
    if (tid == 0) sh = s * (1.f / 512.f);
    __syncthreads();
    float mu = sh;
    float d0 = v0 - mu, d1 = v1 - mu;
    float q = blockReduceSum(d0 * d0 + d1 * d1, red);
    if (tid == 0) sh = rsqrtf(q * (1.f / 512.f) + 1e-5f);
    __syncthreads();
    float rs = sh;
    float z0 = fmaf(d0 * rs, glng[tid],       glnb[tid]);
    float z1 = fmaf(d1 * rs, glng[tid + 256], glnb[tid + 256]);
    float n2 = blockReduceSum(z0 * z0 + z1 * z1, red);
    if (tid == 0) sh = 1.f / sqrtf(n2);
    __syncthreads();
    float rn = sh;
    g_Ghat[b * MI_ + tid]       = z0 * rn;
    g_Ghat[b * MI_ + tid + 256] = z1 * rn;
}

// ---------------- fused LayerNorm + L2-normalize + similarity ----------------
// Per block: 32 bt columns. Computes zhat[:,bt] and directly u[n][bt] =
// dot(Ghat[n], zhat[:,bt]) for all 32 n. No g_Lh materialization.
// Dynamic smem: sGT[512][36] floats (73728 B) + r1/r2 (8x33 each) + stats.
constexpr int LNU_GT    = 512 * 36;                 // floats
constexpr int LNU_SMEM  = (LNU_GT + 2 * 8 * 33 + 96) * 4;

__global__ __launch_bounds__(256) void ln_u(
    const float* __restrict__ lng, const float* __restrict__ lnb)
{
    extern __shared__ float sm[];
    float* sGT = sm;                       // [512][36], also reused as red buf
    float* r1  = sm + LNU_GT;              // [8][33]
    float* r2  = r1 + 8 * 33;
    float* mu_s = r2 + 8 * 33;             // [32]
    float* rs_s = mu_s + 32;
    float* rn_s = rs_s + 32;

    const int q0 = blockIdx.x * 32;
    const int tid = threadIdx.x;
    const int tx = tid & 31, ty = tid >> 5;

    // load Ghat^T into smem: sGT[p][n]
    for (int i = tid; i < 512 * 32; i += 256) {
        int p = i & 511, n = i >> 9;
        sGT[p * 36 + n] = g_Ghat[n * MI_ + p];
    }

    const __half* base = g_Hfh + q0 + tx;

    // pass 1: mean/var over channels
    float s = 0.f, s2 = 0.f;
    for (int p = ty; p < MI_; p += 8) {
        float v = __half2float(base[(size_t)p * NT_]);
        s += v; s2 += v * v;
    }
    r1[ty * 33 + tx] = s; r2[ty * 33 + tx] = s2;
    __syncthreads();
    if (ty == 0) {
        float a = 0.f, c = 0.f;
        #pragma unroll
        for (int i = 0; i < 8; i++) { a += r1[i * 33 + tx]; c += r2[i * 33 + tx]; }
        float mu  = a * (1.f / 512.f);
        float var = c * (1.f / 512.f) - mu * mu;
        mu_s[tx] = mu;
        rs_s[tx] = rsqrtf(var + 1e-5f);
    }
    __syncthreads();
    float mu = mu_s[tx], rs = rs_s[tx];

    // pass 2: L2 norm of z
    float n2 = 0.f;
    for (int p = ty; p < MI_; p += 8) {
        float v = __half2float(base[(size_t)p * NT_]);
        float z = fmaf((v - mu) * rs, lng[p], lnb[p]);
        n2 += z * z;
    }
    __syncthreads();
    r1[ty * 33 + tx] = n2;
    __syncthreads();
    if (ty == 0) {
        float a = 0.f;
        #pragma unroll
        for (int i = 0; i < 8; i++) a += r1[i * 33 + tx];
        rn_s[tx] = rsqrtf(a);
    }
    __syncthreads();
    float rn = rn_s[tx];

    // pass 3: partial dots against all 32 globals (broadcast LDS rows)
    float accv[32];
    #pragma unroll
    for (int n = 0; n < 32; n++) accv[n] = 0.f;
    for (int p = ty; p < MI_; p += 8) {
        float v = __half2float(base[(size_t)p * NT_]);
        float z = fmaf((v - mu) * rs, lng[p], lnb[p]) * rn;
        const float* row = &sGT[p * 36];
        #pragma unroll
        for (int n4 = 0; n4 < 8; n4++) {
            float4 g = *(const float4*)(row + n4 * 4);
            accv[n4 * 4 + 0] = fmaf(z, g.x, accv[n4 * 4 + 0]);
            accv[n4 * 4 + 1] = fmaf(z, g.y, accv[n4 * 4 + 1]);
            accv[n4 * 4 + 2] = fmaf(z, g.z, accv[n4 * 4 + 2]);
            accv[n4 * 4 + 3] = fmaf(z, g.w, accv[n4 * 4 + 3]);
        }
    }

    // reduce over ty (8 partials per (tx, n)); overlay red buffer on sGT
    __syncthreads();
    float* red = sGT;                      // [256][33]
    #pragma unroll
    for (int n = 0; n < 32; n++) red[(ty * 32 + tx) * 33 + n] = accv[n];
    __syncthreads();
    for (int j = tid; j < 1024; j += 256) {
        int txo = j & 31, n = j >> 5;
        float acc = 0.f;
        #pragma unroll
        for (int yy = 0; yy < 8; yy++) acc += red[(yy * 32 + txo) * 33 + n];
        g_uall[(size_t)n * NT_ + q0 + txo] = acc;
    }
}

// ---------------- loss (|u|<=1 -> fixed-shift LSE, no max pass) ---------------
__global__ __launch_bounds__(256) void loss_kernel(float* __restrict__ out)
{
    const int n = blockIdx.x, tid = threadIdx.x;
    const float* u = g_uall + (size_t)n * NT_;
    __shared__ float red[32];
    __shared__ float sh;

    float s = 0.f;
    for (int j = tid; j < NT_; j += 256)
        if ((j >> 8) != n) s += expf(u[j] - 1.0f);
    s = blockReduceSum(s, red);
    if (tid == 0) sh = 1.0f + logf(s);
    __syncthreads();
    float A = sh;

    float p  = u[n * T_ + tid] * (1.f / 0.07f);
    float mx = fmaxf(p, A);
    float c  = p - (mx + logf(expf(p - mx) + expf(A - mx)));
    c = blockReduceSum(c, red);
    if (tid == 0) atomicAdd(out, -c / (float)NT_);
}

// ---------------- launch ------------------------------------------------------
extern "C" void kernel_launch(void* const* d_in, const int* in_sizes, int n_in,
                              void* d_out, int out_size)
{
    const float* x    = (const float*)d_in[0];
    const float* gx   = (const float*)d_in[1];
    const float* lW1  = (const float*)d_in[2];
    const float* lg1  = (const float*)d_in[3];
    const float* lb1  = (const float*)d_in[4];
    const float* lW2  = (const float*)d_in[5];
    const float* lb2  = (const float*)d_in[6];
    const float* lWs  = (const float*)d_in[7];
    const float* llng = (const float*)d_in[8];
    const float* llnb = (const float*)d_in[9];
    const float* gW1  = (const float*)d_in[10];
    const float* gg1  = (const float*)d_in[11];
    const float* gb1  = (const float*)d_in[12];
    const float* gW2  = (const float*)d_in[13];
    const float* gb2  = (const float*)d_in[14];
    const float* gWs  = (const float*)d_in[15];
    const float* glng = (const float*)d_in[16];
    const float* glnb = (const float*)d_in[17];
    float* out = (float*)d_out;

    cudaFuncSetAttribute(gemm_mma<1>, cudaFuncAttributeMaxDynamicSharedMemorySize, GEMM_SMEM);
    cudaFuncSetAttribute(gemm_mma<2>, cudaFuncAttributeMaxDynamicSharedMemorySize, GEMM_SMEM);
    cudaFuncSetAttribute(ln_u, cudaFuncAttributeMaxDynamicSharedMemorySize, LNU_SMEM);

    zero_out<<<1, 512>>>(out);

    // operand prep
    w_to_f16<<<1536, 256>>>(lW1, lWs, lW2);
    split_x<<<dim3(4, 24, 32), 256>>>(x);

    // GEMM1: [W1;Ws] x -> Y1h (+BN partial sums), Hsh
    gemm_mma<1><<<dim3(32, 8), 256, GEMM_SMEM>>>(nullptr);

    bn_finalize<<<1, 512>>>(lg1, lb1);
    split_y<<<dim3(128, 8), 256>>>();

    // GEMM2: W2 relu(bn(Y1)) + b2 + Hs -> Hfh
    gemm_mma<2><<<dim3(32, 4), 256, GEMM_SMEM>>>(lb2);

    // global path (needed before ln_u)
    g_mlp1<<<32, 256>>>(gx, gW1, gWs);
    g_bn<<<1, 512>>>(gg1, gb1);
    g_mlp2<<<32, 256>>>(gW2, gb2);
    g_ln<<<32, 256>>>(glng, glnb);

    // fused LN + L2-normalize + similarity
    ln_u<<<256, 256, LNU_SMEM>>>(llng, llnb);

    loss_kernel<<<32, 256>>>(out);
}

// round 13
// speedup vs baseline: 3.2728x; 1.4875x over previous
#include <cuda_runtime.h>
#include <cuda_fp16.h>
#include <math.h>
#include <cstdint>

// Problem dims (fixed by dataset)
constexpr int B_  = 32;
constexpr int CL_ = 1536;
constexpr int T_  = 256;
constexpr int MI_ = 512;
constexpr int CG_ = 192;
constexpr int NT_ = B_ * T_;          // 8192

// ---------------- scratch (static __device__ — no allocs allowed) -----------
__device__ __half g_X1 [(size_t)NT_ * CL_];   // fp16(x)^T      [bt][c]
__device__ __half g_Wf [(size_t)1024 * CL_];  // [W1;Ws] fp16
__device__ __half g_X2 [(size_t)NT_ * MI_];   // fp16(relu(bn(Y1)))^T [bt][o]
__device__ __half g_W2f[(size_t)MI_ * MI_];   // W2 fp16
__device__ __half g_Y1h[(size_t)MI_ * NT_];   // conv1 out   [o][bt] fp16
__device__ __half g_Hsh[(size_t)MI_ * NT_];   // shortcut    [o][bt] fp16
__device__ __half g_Hfh[(size_t)MI_ * NT_];   // final h     [o][bt] fp16
__device__ float g_W1t[(size_t)CG_ * MI_];    // gW1^T [k][o]
__device__ float g_Wst[(size_t)CG_ * MI_];    // gWs^T
__device__ float g_W2t[(size_t)MI_ * MI_];    // gW2^T
__device__ float g_bnsum[MI_], g_bnsum2[MI_];
__device__ float g_yg[B_ * MI_], g_hg[B_ * MI_];
__device__ float g_Ghat[B_ * MI_];
__device__ float g_S[B_];                     // per-n negative exp-sums
__device__ float g_upos[B_ * T_];             // positives (already / TEMP)

// ---------------- small helpers ----------------------------------------------
__device__ __forceinline__ uint32_t smem_u32(const void* p) {
    uint32_t a;
    asm("{ .reg .u64 t; cvta.to.shared.u64 t, %1; cvt.u32.u64 %0, t; }"
        : "=r"(a) : "l"(p));
    return a;
}
__device__ __forceinline__ void cp_async16(uint32_t saddr, const void* gaddr) {
    asm volatile("cp.async.cg.shared.global [%0], [%1], 16;"
                 :: "r"(saddr), "l"(gaddr) : "memory");
}
__device__ __forceinline__ void cp_commit() {
    asm volatile("cp.async.commit_group;" ::: "memory");
}
template<int N>
__device__ __forceinline__ void cp_wait() {
    asm volatile("cp.async.wait_group %0;" :: "n"(N) : "memory");
}
__device__ __forceinline__ void ldsm_x4(uint32_t* r, uint32_t addr) {
    asm volatile("ldmatrix.sync.aligned.m8n8.x4.shared.b16 {%0,%1,%2,%3}, [%4];"
                 : "=r"(r[0]), "=r"(r[1]), "=r"(r[2]), "=r"(r[3]) : "r"(addr));
}
__device__ __forceinline__ void mma_f16(float* d, const uint32_t* a,
                                        uint32_t b0, uint32_t b1) {
    asm volatile("mma.sync.aligned.m16n8k16.row.col.f32.f16.f16.f32 "
                 "{%0,%1,%2,%3}, {%4,%5,%6,%7}, {%8,%9}, {%0,%1,%2,%3};"
                 : "+f"(d[0]), "+f"(d[1]), "+f"(d[2]), "+f"(d[3])
                 : "r"(a[0]), "r"(a[1]), "r"(a[2]), "r"(a[3]), "r"(b0), "r"(b1));
}

__device__ __forceinline__ float blockReduceSum(float v, float* red) {
    __syncthreads();
    #pragma unroll
    for (int o = 16; o; o >>= 1) v += __shfl_xor_sync(0xffffffffu, v, o);
    int lane = threadIdx.x & 31, wid = threadIdx.x >> 5;
    if (lane == 0) red[wid] = v;
    __syncthreads();
    if (threadIdx.x < 32) {
        float t = (threadIdx.x < (blockDim.x >> 5)) ? red[threadIdx.x] : 0.f;
        #pragma unroll
        for (int o = 4; o; o >>= 1) t += __shfl_xor_sync(0xffffffffu, t, o);
        if (threadIdx.x == 0) red[0] = t;
    }
    __syncthreads();
    return red[0];
}

// ---------------- prep: weight fp16 conversion + global-W transposes + zero ---
// blocks: [0,1024) lW conv; [1024,1536) lW2 conv; [1536,1632) gW1^T;
//         [1632,1728) gWs^T; [1728,1984) gW2^T; 1984 zero.
__global__ __launch_bounds__(256) void prep(
    const float* __restrict__ W1, const float* __restrict__ Ws,
    const float* __restrict__ W2,
    const float* __restrict__ gW1, const float* __restrict__ gWs,
    const float* __restrict__ gW2)
{
    __shared__ float tile[32][33];
    const int r = blockIdx.x, tid = threadIdx.x;
    if (r < 1024) {
        const float* src = (r < 512) ? (W1 + (size_t)r * CL_)
                                     : (Ws + (size_t)(r - 512) * CL_);
        for (int c2 = tid * 2; c2 < CL_; c2 += 512)
            *(__half2*)&g_Wf[(size_t)r * CL_ + c2] =
                __floats2half2_rn(src[c2], src[c2 + 1]);
    } else if (r < 1536) {
        const int rr = r - 1024;
        const int c2 = tid * 2;
        *(__half2*)&g_W2f[(size_t)rr * MI_ + c2] =
            __floats2half2_rn(W2[(size_t)rr * MI_ + c2], W2[(size_t)rr * MI_ + c2 + 1]);
    } else if (r < 1984) {
        const int seg = r - 1536;
        const float* src; float* dst; int C, ti, tj;
        if (seg < 192) {
            const int s2 = seg % 96;
            src = (seg < 96) ? gW1 : gWs;
            dst = (seg < 96) ? g_W1t : g_Wst;
            C = CG_; ti = s2 / 6; tj = s2 % 6;     // 16 x 6 tiles of 32x32
        } else {
            const int s2 = seg - 192;
            src = gW2; dst = g_W2t;
            C = MI_; ti = s2 >> 4; tj = s2 & 15;   // 16 x 16 tiles
        }
        const int tx = tid & 31, ty = tid >> 5;    // 8 rows per pass
        #pragma unroll
        for (int rr = ty; rr < 32; rr += 8)
            tile[rr][tx] = src[(size_t)(ti * 32 + rr) * C + tj * 32 + tx];
        __syncthreads();
        #pragma unroll
        for (int rr = ty; rr < 32; rr += 8)
            dst[(size_t)(tj * 32 + rr) * MI_ + ti * 32 + tx] = tile[tx][rr];
    } else {
        if (tid < 32) g_S[tid] = 0.f;
        g_bnsum[tid] = 0.f;       g_bnsum2[tid] = 0.f;
        g_bnsum[tid + 256] = 0.f; g_bnsum2[tid + 256] = 0.f;
    }
}

// x [b][c][t] fp32 -> X1 [bt][c] fp16 (transpose + round)
__global__ __launch_bounds__(256) void split_x(const float* __restrict__ x)
{
    __shared__ float tile[64][65];
    const int b = blockIdx.z, c0 = blockIdx.y * 64, t0 = blockIdx.x * 64;
    const int tid = threadIdx.x;
    #pragma unroll
    for (int it = 0; it < 16; it++) {
        int i = it * 256 + tid, c = i >> 6, t = i & 63;
        tile[c][t] = x[((size_t)b * CL_ + c0 + c) * T_ + t0 + t];
    }
    __syncthreads();
    #pragma unroll
    for (int it = 0; it < 8; it++) {
        int i = it * 256 + tid, r = i >> 5, c2 = (i & 31) * 2;
        *(__half2*)&g_X1[(size_t)(b * T_ + t0 + r) * CL_ + c0 + c2] =
            __floats2half2_rn(tile[c2][r], tile[c2 + 1][r]);
    }
}

// relu(bn(Y1h)) [o][bt] -> X2 [bt][o] fp16 ; BN finalize fused per block
__global__ __launch_bounds__(256) void split_y(const float* __restrict__ g1,
                                               const float* __restrict__ b1)
{
    __shared__ float tile[64][65];
    __shared__ float ssc[64], ssh[64];
    const int o0 = blockIdx.y * 64, q0 = blockIdx.x * 64;
    const int tid = threadIdx.x;
    if (tid < 64) {
        const int o = o0 + tid;
        float mu  = g_bnsum[o]  * (1.f / 8192.f);
        float var = g_bnsum2[o] * (1.f / 8192.f) - mu * mu;
        float sc  = rsqrtf(var + 1e-5f) * g1[o];
        ssc[tid] = sc;
        ssh[tid] = fmaf(-mu, sc, b1[o]);
    }
    __syncthreads();
    #pragma unroll
    for (int it = 0; it < 8; it++) {
        int i = it * 256 + tid, c = i >> 5, t2 = (i & 31) * 2;
        __half2 hv = *(const __half2*)&g_Y1h[(size_t)(o0 + c) * NT_ + q0 + t2];
        float2 v = __half22float2(hv);
        float sc = ssc[c], sh = ssh[c];
        tile[c][t2]     = fmaxf(fmaf(v.x, sc, sh), 0.f);
        tile[c][t2 + 1] = fmaxf(fmaf(v.y, sc, sh), 0.f);
    }
    __syncthreads();
    #pragma unroll
    for (int it = 0; it < 8; it++) {
        int i = it * 256 + tid, r = i >> 5, c2 = (i & 31) * 2;
        *(__half2*)&g_X2[(size_t)(q0 + r) * MI_ + o0 + c2] =
            __floats2half2_rn(tile[c2][r], tile[c2 + 1][r]);
    }
}

// ---------------- HMMA GEMM (mma.sync fp16, fp32 accum) -----------------------
constexpr int KPAD   = 80;
constexpr int A_BYT  = 128 * KPAD;
constexpr int STG_SZ = A_BYT + 256 * KPAD;
constexpr int NSTG   = 3;
constexpr int GEMM_SMEM = NSTG * STG_SZ;

template<int MODE>
__global__ __launch_bounds__(256, 1) void gemm_mma(const float* __restrict__ bias)
{
    constexpr int REG   = (MODE == 1) ? CL_ : MI_;
    constexpr int ITERS = REG / 32;
    const __half* __restrict__ A  = (MODE == 1) ? g_Wf : g_W2f;
    const __half* __restrict__ Bm = (MODE == 1) ? g_X1 : g_X2;

    extern __shared__ char smem[];
    const uint32_t sbase = smem_u32(smem);
    const int tid = threadIdx.x, wid = tid >> 5, lane = tid & 31;
    const int n0 = blockIdx.x * 256;
    const int m0 = blockIdx.y * 128;

    const int lr4 = tid >> 2, lc4 = tid & 3;

    auto load_stage = [&](int stg, int kc) {
        const int k0 = kc * 32;
        const uint32_t sa = sbase + stg * STG_SZ;
        const uint32_t sb = sa + A_BYT;
        cp_async16(sa + lr4 * KPAD + lc4 * 16,
                   A + (size_t)(m0 + lr4) * REG + k0 + lc4 * 8);
        cp_async16(sa + (64 + lr4) * KPAD + lc4 * 16,
                   A + (size_t)(m0 + 64 + lr4) * REG + k0 + lc4 * 8);
        #pragma unroll
        for (int j = 0; j < 4; j++)
            cp_async16(sb + (j * 64 + lr4) * KPAD + lc4 * 16,
                       Bm + (size_t)(n0 + j * 64 + lr4) * REG + k0 + lc4 * 8);
    };

    const int wm = (wid >> 2) * 64;
    const int wn = (wid & 3) * 64;
    const int mi = lane >> 3, lr = lane & 7;
    const int rowA = wm + (mi & 1) * 8 + lr;
    const int rowB = wn + (mi & 1) * 8 + lr;
    const int colK = (mi >> 1) * 16;

    float acc[4][8][4];
    #pragma unroll
    for (int a = 0; a < 4; a++)
        #pragma unroll
        for (int b = 0; b < 8; b++)
            #pragma unroll
            for (int c = 0; c < 4; c++) acc[a][b][c] = 0.f;

    load_stage(0, 0); cp_commit();
    load_stage(1, 1); cp_commit();

    for (int kc = 0; kc < ITERS; kc++) {
        cp_wait<1>();
        __syncthreads();
        const int stg = kc % NSTG;
        if (kc + 2 < ITERS) load_stage((kc + 2) % NSTG, kc + 2);
        cp_commit();

        const uint32_t sA = sbase + stg * STG_SZ;
        const uint32_t sB = sA + A_BYT;
        #pragma unroll
        for (int kh = 0; kh < 2; kh++) {
            uint32_t af[4][4], bf[4][4];
            #pragma unroll
            for (int mt = 0; mt < 4; mt++)
                ldsm_x4(af[mt], sA + (uint32_t)(rowA + mt * 16) * KPAD + kh * 32 + colK);
            #pragma unroll
            for (int ntp = 0; ntp < 4; ntp++)
                ldsm_x4(bf[ntp], sB + (uint32_t)(rowB + ntp * 16) * KPAD + kh * 32 + colK);
            #pragma unroll
            for (int mt = 0; mt < 4; mt++)
                #pragma unroll
                for (int nt = 0; nt < 8; nt++)
                    mma_f16(acc[mt][nt], af[mt],
                            bf[nt >> 1][nt & 1], bf[nt >> 1][2 + (nt & 1)]);
        }
    }

    const int er = m0 + wm + (lane >> 2);
    const int ec = n0 + wn + (lane & 3) * 2;
    #pragma unroll
    for (int mt = 0; mt < 4; mt++) {
        #pragma unroll
        for (int half = 0; half < 2; half++) {
            const int row = er + mt * 16 + half * 8;
            float s = 0.f, s2 = 0.f;
            #pragma unroll
            for (int nt = 0; nt < 8; nt++) {
                const int col = ec + nt * 8;
                float v0 = acc[mt][nt][half * 2 + 0];
                float v1 = acc[mt][nt][half * 2 + 1];
                if (MODE == 1) {
                    __half2* dst = (row < 512)
                        ? (__half2*)(g_Y1h + (size_t)row * NT_ + col)
                        : (__half2*)(g_Hsh + (size_t)(row - 512) * NT_ + col);
                    *dst = __floats2half2_rn(v0, v1);
                    s += v0 + v1; s2 += v0 * v0 + v1 * v1;
                } else {
                    const float bv = bias[row];
                    float2 h = __half22float2(
                        *(const __half2*)(g_Hsh + (size_t)row * NT_ + col));
                    *(__half2*)(g_Hfh + (size_t)row * NT_ + col) =
                        __floats2half2_rn(v0 + bv + h.x, v1 + bv + h.y);
                }
            }
            if (MODE == 1 && row < 512) {
                s  += __shfl_xor_sync(0xffffffffu, s, 1);
                s  += __shfl_xor_sync(0xffffffffu, s, 2);
                s2 += __shfl_xor_sync(0xffffffffu, s2, 1);
                s2 += __shfl_xor_sync(0xffffffffu, s2, 2);
                if ((lane & 3) == 0) {
                    atomicAdd(&g_bnsum[row], s);
                    atomicAdd(&g_bnsum2[row], s2);
                }
            }
        }
    }
}

// ---------------- Global path (coalesced via transposed weights) --------------
// g_front: block b, 512 threads; o = tid
__global__ __launch_bounds__(512) void g_front(const float* __restrict__ gx)
{
    __shared__ float xs[CG_];
    const int b = blockIdx.x, tid = threadIdx.x;
    if (tid < CG_) xs[tid] = gx[b * CG_ + tid];
    __syncthreads();
    float a = 0.f, c = 0.f;
    #pragma unroll 4
    for (int k = 0; k < CG_; k++) {
        float xv = xs[k];
        a = fmaf(g_W1t[(size_t)k * MI_ + tid], xv, a);
        c = fmaf(g_Wst[(size_t)k * MI_ + tid], xv, c);
    }
    g_yg[b * MI_ + tid] = a;
    g_hg[b * MI_ + tid] = c;
}

// g_tail: block b, 512 threads: BN (per-thread channel stats) + relu + MLP2 +
// shortcut + LayerNorm + L2 normalize -> Ghat
__global__ __launch_bounds__(512) void g_tail(
    const float* __restrict__ gg1, const float* __restrict__ gb1,
    const float* __restrict__ gb2,
    const float* __restrict__ glng, const float* __restrict__ glnb)
{
    __shared__ float a[MI_];
    __shared__ float red[32];
    __shared__ float sh;
    const int b = blockIdx.x, o = threadIdx.x;

    // per-channel BN stats over batch (coalesced across threads)
    float s = 0.f, s2 = 0.f;
    #pragma unroll
    for (int bb = 0; bb < B_; bb++) {
        float v = g_yg[bb * MI_ + o];
        s += v; s2 += v * v;
    }
    float mu  = s  * (1.f / 32.f);
    float var = s2 * (1.f / 32.f) - mu * mu;
    float sc  = rsqrtf(var + 1e-5f) * gg1[o];
    float shv = fmaf(-mu, sc, gb1[o]);
    a[o] = fmaxf(fmaf(g_yg[b * MI_ + o], sc, shv), 0.f);
    __syncthreads();

    // MLP2 (coalesced W2t reads, smem-broadcast activations)
    float acc = 0.f;
    #pragma unroll 4
    for (int k = 0; k < MI_; k++)
        acc = fmaf(g_W2t[(size_t)k * MI_ + o], a[k], acc);
    float h = acc + gb2[o] + g_hg[b * MI_ + o];

    // LayerNorm + L2 normalize
    float ms = blockReduceSum(h, red);
    if (o == 0) sh = ms * (1.f / 512.f);
    __syncthreads();
    float lmu = sh;
    float d = h - lmu;
    float q = blockReduceSum(d * d, red);
    if (o == 0) sh = rsqrtf(q * (1.f / 512.f) + 1e-5f);
    __syncthreads();
    float lrs = sh;
    float z = fmaf(d * lrs, glng[o], glnb[o]);
    float n2 = blockReduceSum(z * z, red);
    if (o == 0) sh = rsqrtf(n2);
    __syncthreads();
    g_Ghat[b * MI_ + o] = z * sh;
}

// ---------------- fused LN + L2-normalize + similarity + loss partials --------
// Per block: 32 bt columns (all same sample b). Computes u[n][col] for all n,
// accumulates sum(exp(u-1)) into g_S[n] (n != b) and writes positives (n == b).
constexpr int LNU_GT   = 512 * 36;
constexpr int LNU_EXP  = 32 * 33;
constexpr int LNU_SMEM = (LNU_GT + 2 * 8 * 33 + 96 + LNU_EXP) * 4;

__global__ __launch_bounds__(256) void ln_u(
    const float* __restrict__ lng, const float* __restrict__ lnb)
{
    extern __shared__ float sm[];
    float* sGT  = sm;                      // [512][36], pass3-red overlays here
    float* r1   = sm + LNU_GT;             // [8][33]
    float* r2   = r1 + 8 * 33;
    float* mu_s = r2 + 8 * 33;             // [32]
    float* rs_s = mu_s + 32;
    float* rn_s = rs_s + 32;
    float* sE   = rn_s + 32;               // [32][33] exp values

    const int q0 = blockIdx.x * 32;
    const int bblk = q0 >> 8;              // sample index of these columns
    const int tid = threadIdx.x;
    const int tx = tid & 31, ty = tid >> 5;

    for (int i = tid; i < 512 * 32; i += 256) {
        int p = i & 511, n = i >> 9;
        sGT[p * 36 + n] = g_Ghat[n * MI_ + p];
    }

    const __half* base = g_Hfh + q0 + tx;

    float s = 0.f, s2 = 0.f;
    for (int p = ty; p < MI_; p += 8) {
        float v = __half2float(base[(size_t)p * NT_]);
        s += v; s2 += v * v;
    }
    r1[ty * 33 + tx] = s; r2[ty * 33 + tx] = s2;
    __syncthreads();
    if (ty == 0) {
        float a = 0.f, c = 0.f;
        #pragma unroll
        for (int i = 0; i < 8; i++) { a += r1[i * 33 + tx]; c += r2[i * 33 + tx]; }
        float mu  = a * (1.f / 512.f);
        float var = c * (1.f / 512.f) - mu * mu;
        mu_s[tx] = mu;
        rs_s[tx] = rsqrtf(var + 1e-5f);
    }
    __syncthreads();
    float mu = mu_s[tx], rs = rs_s[tx];

    float n2 = 0.f;
    for (int p = ty; p < MI_; p += 8) {
        float v = __half2float(base[(size_t)p * NT_]);
        float z = fmaf((v - mu) * rs, lng[p], lnb[p]);
        n2 += z * z;
    }
    __syncthreads();
    r1[ty * 33 + tx] = n2;
    __syncthreads();
    if (ty == 0) {
        float a = 0.f;
        #pragma unroll
        for (int i = 0; i < 8; i++) a += r1[i * 33 + tx];
        rn_s[tx] = rsqrtf(a);
    }
    __syncthreads();
    float rn = rn_s[tx];

    float accv[32];
    #pragma unroll
    for (int n = 0; n < 32; n++) accv[n] = 0.f;
    for (int p = ty; p < MI_; p += 8) {
        float v = __half2float(base[(size_t)p * NT_]);
        float z = fmaf((v - mu) * rs, lng[p], lnb[p]) * rn;
        const float* row = &sGT[p * 36];
        #pragma unroll
        for (int n4 = 0; n4 < 8; n4++) {
            float4 g = *(const float4*)(row + n4 * 4);
            accv[n4 * 4 + 0] = fmaf(z, g.x, accv[n4 * 4 + 0]);
            accv[n4 * 4 + 1] = fmaf(z, g.y, accv[n4 * 4 + 1]);
            accv[n4 * 4 + 2] = fmaf(z, g.z, accv[n4 * 4 + 2]);
            accv[n4 * 4 + 3] = fmaf(z, g.w, accv[n4 * 4 + 3]);
        }
    }

    __syncthreads();
    float* red = sGT;                      // reuse as [256][33]
    #pragma unroll
    for (int n = 0; n < 32; n++) red[(ty * 32 + tx) * 33 + n] = accv[n];
    __syncthreads();
    for (int j = tid; j < 1024; j += 256) {
        int txo = j & 31, n = j >> 5;
        float acc = 0.f;
        #pragma unroll
        for (int yy = 0; yy < 8; yy++) acc += red[(yy * 32 + txo) * 33 + n];
        if (n == bblk) {
            g_upos[n * T_ + (q0 & 255) + txo] = acc * (1.f / 0.07f);
            sE[n * 33 + txo] = 0.f;
        } else {
            sE[n * 33 + txo] = expf(acc - 1.0f);
        }
    }
    __syncthreads();
    if (tid < 32 && tid != bblk) {
        float t = 0.f;
        #pragma unroll
        for (int c = 0; c < 32; c++) t += sE[tid * 33 + c];
        atomicAdd(&g_S[tid], t);
    }
}

// ---------------- final loss (1 block) ----------------------------------------
__global__ __launch_bounds__(256) void loss_final(float* __restrict__ out)
{
    __shared__ float A[32];
    __shared__ float red[32];
    const int tid = threadIdx.x;
    if (tid < 32) A[tid] = 1.0f + logf(g_S[tid]);
    __syncthreads();
    float c = 0.f;
    for (int j = tid; j < NT_; j += 256) {
        int n = j >> 8;
        float p  = g_upos[j];
        float An = A[n];
        float mx = fmaxf(p, An);
        c += p - (mx + logf(expf(p - mx) + expf(An - mx)));
    }
    c = blockReduceSum(c, red);
    if (tid == 0) *out = -c / (float)NT_;
}

// ---------------- launch ------------------------------------------------------
extern "C" void kernel_launch(void* const* d_in, const int* in_sizes, int n_in,
                              void* d_out, int out_size)
{
    const float* x    = (const float*)d_in[0];
    const float* gx   = (const float*)d_in[1];
    const float* lW1  = (const float*)d_in[2];
    const float* lg1  = (const float*)d_in[3];
    const float* lb1  = (const float*)d_in[4];
    const float* lW2  = (const float*)d_in[5];
    const float* lb2  = (const float*)d_in[6];
    const float* lWs  = (const float*)d_in[7];
    const float* llng = (const float*)d_in[8];
    const float* llnb = (const float*)d_in[9];
    const float* gW1  = (const float*)d_in[10];
    const float* gg1  = (const float*)d_in[11];
    const float* gb1  = (const float*)d_in[12];
    const float* gW2  = (const float*)d_in[13];
    const float* gb2  = (const float*)d_in[14];
    const float* gWs  = (const float*)d_in[15];
    const float* glng = (const float*)d_in[16];
    const float* glnb = (const float*)d_in[17];
    float* out = (float*)d_out;

    cudaFuncSetAttribute(gemm_mma<1>, cudaFuncAttributeMaxDynamicSharedMemorySize, GEMM_SMEM);
    cudaFuncSetAttribute(gemm_mma<2>, cudaFuncAttributeMaxDynamicSharedMemorySize, GEMM_SMEM);
    cudaFuncSetAttribute(ln_u, cudaFuncAttributeMaxDynamicSharedMemorySize, LNU_SMEM);

    prep<<<1985, 256>>>(lW1, lWs, lW2, gW1, gWs, gW2);
    split_x<<<dim3(4, 24, 32), 256>>>(x);

    gemm_mma<1><<<dim3(32, 8), 256, GEMM_SMEM>>>(nullptr);
    split_y<<<dim3(128, 8), 256>>>(lg1, lb1);
    gemm_mma<2><<<dim3(32, 4), 256, GEMM_SMEM>>>(lb2);

    g_front<<<32, 512>>>(gx);
    g_tail<<<32, 512>>>(gg1, gb1, gb2, glng, glnb);

    ln_u<<<256, 256, LNU_SMEM>>>(llng, llnb);
    loss_final<<<1, 256>>>(out);
}

// round 16
// speedup vs baseline: 3.3888x; 1.0355x over previous
#include <cuda_runtime.h>
#include <cuda_fp16.h>
#include <math.h>
#include <cstdint>

// Problem dims (fixed by dataset)
constexpr int B_  = 32;
constexpr int CL_ = 1536;
constexpr int T_  = 256;
constexpr int MI_ = 512;
constexpr int CG_ = 192;
constexpr int NT_ = B_ * T_;          // 8192

// ---------------- scratch (static __device__ — no allocs allowed) -----------
__device__ __half g_X1 [(size_t)NT_ * CL_];   // fp16(x)^T      [bt][c]
__device__ __half g_Wf [(size_t)1024 * CL_];  // [W1;Ws] fp16
__device__ __half g_X2 [(size_t)NT_ * MI_];   // fp16(relu(bn(Y1)))^T [bt][o]
__device__ __half g_W2f[(size_t)MI_ * MI_];   // W2 fp16
__device__ __half g_Y1h[(size_t)MI_ * NT_];   // conv1 out   [o][bt] fp16
__device__ __half g_Hsh[(size_t)MI_ * NT_];   // shortcut    [o][bt] fp16
__device__ __half g_Hfh[(size_t)MI_ * NT_];   // final h     [o][bt] fp16
__device__ float g_W1t[(size_t)CG_ * MI_];    // gW1^T [k][o]
__device__ float g_Wst[(size_t)CG_ * MI_];    // gWs^T
__device__ float g_W2t[(size_t)MI_ * MI_];    // gW2^T
__device__ float g_bnsum[MI_], g_bnsum2[MI_];
__device__ float g_yg[B_ * MI_], g_hg[B_ * MI_];
__device__ float g_Ghat[B_ * MI_];
__device__ float g_S[B_];                     // per-n negative exp-sums
__device__ float g_upos[B_ * T_];             // positives (already / TEMP)

// ---------------- small helpers ----------------------------------------------
__device__ __forceinline__ uint32_t smem_u32(const void* p) {
    uint32_t a;
    asm("{ .reg .u64 t; cvta.to.shared.u64 t, %1; cvt.u32.u64 %0, t; }"
        : "=r"(a) : "l"(p));
    return a;
}
__device__ __forceinline__ void cp_async16(uint32_t saddr, const void* gaddr) {
    asm volatile("cp.async.cg.shared.global [%0], [%1], 16;"
                 :: "r"(saddr), "l"(gaddr) : "memory");
}
__device__ __forceinline__ void cp_commit() {
    asm volatile("cp.async.commit_group;" ::: "memory");
}
template<int N>
__device__ __forceinline__ void cp_wait() {
    asm volatile("cp.async.wait_group %0;" :: "n"(N) : "memory");
}
__device__ __forceinline__ void ldsm_x4(uint32_t* r, uint32_t addr) {
    asm volatile("ldmatrix.sync.aligned.m8n8.x4.shared.b16 {%0,%1,%2,%3}, [%4];"
                 : "=r"(r[0]), "=r"(r[1]), "=r"(r[2]), "=r"(r[3]) : "r"(addr));
}
// fp16-accumulator HMMA (possible 2x rate vs f32 accum on legacy path)
__device__ __forceinline__ void mma_f16acc(uint32_t* d, const uint32_t* a,
                                           uint32_t b0, uint32_t b1) {
    asm volatile("mma.sync.aligned.m16n8k16.row.col.f16.f16.f16.f16 "
                 "{%0,%1}, {%2,%3,%4,%5}, {%6,%7}, {%0,%1};"
                 : "+r"(d[0]), "+r"(d[1])
                 : "r"(a[0]), "r"(a[1]), "r"(a[2]), "r"(a[3]), "r"(b0), "r"(b1));
}

__device__ __forceinline__ float blockReduceSum(float v, float* red) {
    __syncthreads();
    #pragma unroll
    for (int o = 16; o; o >>= 1) v += __shfl_xor_sync(0xffffffffu, v, o);
    int lane = threadIdx.x & 31, wid = threadIdx.x >> 5;
    if (lane == 0) red[wid] = v;
    __syncthreads();
    if (threadIdx.x < 32) {
        float t = (threadIdx.x < (blockDim.x >> 5)) ? red[threadIdx.x] : 0.f;
        #pragma unroll
        for (int o = 4; o; o >>= 1) t += __shfl_xor_sync(0xffffffffu, t, o);
        if (threadIdx.x == 0) red[0] = t;
    }
    __syncthreads();
    return red[0];
}

// ---------------- prep (weights + transposes + zero) AND x transpose ----------
// blocks: [0,1024) lW conv; [1024,1536) lW2 conv; [1536,1632) gW1^T;
//         [1632,1728) gWs^T; [1728,1984) gW2^T; 1984 zero; [1985,5057) split_x.
__global__ __launch_bounds__(256) void prep_all(
    const float* __restrict__ W1, const float* __restrict__ Ws,
    const float* __restrict__ W2,
    const float* __restrict__ gW1, const float* __restrict__ gWs,
    const float* __restrict__ gW2, const float* __restrict__ x)
{
    __shared__ float tile[64][65];
    const int r = blockIdx.x, tid = threadIdx.x;
    if (r < 1024) {
        const float* src = (r < 512) ? (W1 + (size_t)r * CL_)
                                     : (Ws + (size_t)(r - 512) * CL_);
        for (int c2 = tid * 2; c2 < CL_; c2 += 512)
            *(__half2*)&g_Wf[(size_t)r * CL_ + c2] =
                __floats2half2_rn(src[c2], src[c2 + 1]);
    } else if (r < 1536) {
        const int rr = r - 1024;
        const int c2 = tid * 2;
        *(__half2*)&g_W2f[(size_t)rr * MI_ + c2] =
            __floats2half2_rn(W2[(size_t)rr * MI_ + c2], W2[(size_t)rr * MI_ + c2 + 1]);
    } else if (r < 1984) {
        const int seg = r - 1536;
        const float* src; float* dst; int C, ti, tj;
        if (seg < 192) {
            const int s2 = seg % 96;
            src = (seg < 96) ? gW1 : gWs;
            dst = (seg < 96) ? g_W1t : g_Wst;
            C = CG_; ti = s2 / 6; tj = s2 % 6;
        } else {
            const int s2 = seg - 192;
            src = gW2; dst = g_W2t;
            C = MI_; ti = s2 >> 4; tj = s2 & 15;
        }
        const int tx = tid & 31, ty = tid >> 5;
        #pragma unroll
        for (int rr = ty; rr < 32; rr += 8)
            tile[rr][tx] = src[(size_t)(ti * 32 + rr) * C + tj * 32 + tx];
        __syncthreads();
        #pragma unroll
        for (int rr = ty; rr < 32; rr += 8)
            dst[(size_t)(tj * 32 + rr) * MI_ + ti * 32 + tx] = tile[tx][rr];
    } else if (r == 1984) {
        if (tid < 32) g_S[tid] = 0.f;
        g_bnsum[tid] = 0.f;       g_bnsum2[tid] = 0.f;
        g_bnsum[tid + 256] = 0.f; g_bnsum2[tid + 256] = 0.f;
    } else {
        // split_x: s in [0, 3072) -> t0, c0, b
        const int s = r - 1985;
        const int t0 = (s & 3) * 64;
        const int c0 = ((s >> 2) % 24) * 64;
        const int b  = s / 96;
        #pragma unroll
        for (int it = 0; it < 16; it++) {
            int i = it * 256 + tid, c = i >> 6, t = i & 63;
            tile[c][t] = x[((size_t)b * CL_ + c0 + c) * T_ + t0 + t];
        }
        __syncthreads();
        #pragma unroll
        for (int it = 0; it < 8; it++) {
            int i = it * 256 + tid, rr = i >> 5, c2 = (i & 31) * 2;
            *(__half2*)&g_X1[(size_t)(b * T_ + t0 + rr) * CL_ + c0 + c2] =
                __floats2half2_rn(tile[c2][rr], tile[c2 + 1][rr]);
        }
    }
}

// relu(bn(Y1h)) [o][bt] -> X2 [bt][o] fp16 ; BN finalize fused per block
__global__ __launch_bounds__(256) void split_y(const float* __restrict__ g1,
                                               const float* __restrict__ b1)
{
    __shared__ float tile[64][65];
    __shared__ float ssc[64], ssh[64];
    const int o0 = blockIdx.y * 64, q0 = blockIdx.x * 64;
    const int tid = threadIdx.x;
    if (tid < 64) {
        const int o = o0 + tid;
        float mu  = g_bnsum[o]  * (1.f / 8192.f);
        float var = g_bnsum2[o] * (1.f / 8192.f) - mu * mu;
        float sc  = rsqrtf(var + 1e-5f) * g1[o];
        ssc[tid] = sc;
        ssh[tid] = fmaf(-mu, sc, b1[o]);
    }
    __syncthreads();
    #pragma unroll
    for (int it = 0; it < 8; it++) {
        int i = it * 256 + tid, c = i >> 5, t2 = (i & 31) * 2;
        __half2 hv = *(const __half2*)&g_Y1h[(size_t)(o0 + c) * NT_ + q0 + t2];
        float2 v = __half22float2(hv);
        float sc = ssc[c], sh = ssh[c];
        tile[c][t2]     = fmaxf(fmaf(v.x, sc, sh), 0.f);
        tile[c][t2 + 1] = fmaxf(fmaf(v.y, sc, sh), 0.f);
    }
    __syncthreads();
    #pragma unroll
    for (int it = 0; it < 8; it++) {
        int i = it * 256 + tid, r = i >> 5, c2 = (i & 31) * 2;
        *(__half2*)&g_X2[(size_t)(q0 + r) * MI_ + o0 + c2] =
            __floats2half2_rn(tile[c2][r], tile[c2 + 1][r]);
    }
}

// ---------------- HMMA GEMM (mma.sync fp16, fp16 accum) -----------------------
constexpr int KPAD   = 80;
constexpr int A_BYT  = 128 * KPAD;
constexpr int STG_SZ = A_BYT + 256 * KPAD;
constexpr int NSTG   = 3;
constexpr int GEMM_SMEM = NSTG * STG_SZ;

template<int MODE>
__global__ __launch_bounds__(256, 1) void gemm_mma(const float* __restrict__ bias)
{
    constexpr int REG   = (MODE == 1) ? CL_ : MI_;
    constexpr int ITERS = REG / 32;
    const __half* __restrict__ A  = (MODE == 1) ? g_Wf : g_W2f;
    const __half* __restrict__ Bm = (MODE == 1) ? g_X1 : g_X2;

    extern __shared__ char smem[];
    const uint32_t sbase = smem_u32(smem);
    const int tid = threadIdx.x, wid = tid >> 5, lane = tid & 31;
    const int n0 = blockIdx.x * 256;
    const int m0 = blockIdx.y * 128;

    const int lr4 = tid >> 2, lc4 = tid & 3;

    auto load_stage = [&](int stg, int kc) {
        const int k0 = kc * 32;
        const uint32_t sa = sbase + stg * STG_SZ;
        const uint32_t sb = sa + A_BYT;
        cp_async16(sa + lr4 * KPAD + lc4 * 16,
                   A + (size_t)(m0 + lr4) * REG + k0 + lc4 * 8);
        cp_async16(sa + (64 + lr4) * KPAD + lc4 * 16,
                   A + (size_t)(m0 + 64 + lr4) * REG + k0 + lc4 * 8);
        #pragma unroll
        for (int j = 0; j < 4; j++)
            cp_async16(sb + (j * 64 + lr4) * KPAD + lc4 * 16,
                       Bm + (size_t)(n0 + j * 64 + lr4) * REG + k0 + lc4 * 8);
    };

    const int wm = (wid >> 2) * 64;
    const int wn = (wid & 3) * 64;
    const int mi = lane >> 3, lr = lane & 7;
    const int rowA = wm + (mi & 1) * 8 + lr;
    const int rowB = wn + (mi & 1) * 8 + lr;
    const int colK = (mi >> 1) * 16;

    uint32_t acc[4][8][2];
    #pragma unroll
    for (int a = 0; a < 4; a++)
        #pragma unroll
        for (int b = 0; b < 8; b++) { acc[a][b][0] = 0u; acc[a][b][1] = 0u; }

    load_stage(0, 0); cp_commit();
    load_stage(1, 1); cp_commit();

    for (int kc = 0; kc < ITERS; kc++) {
        cp_wait<1>();
        __syncthreads();
        const int stg = kc % NSTG;
        if (kc + 2 < ITERS) load_stage((kc + 2) % NSTG, kc + 2);
        cp_commit();

        const uint32_t sA = sbase + stg * STG_SZ;
        const uint32_t sB = sA + A_BYT;
        #pragma unroll
        for (int kh = 0; kh < 2; kh++) {
            uint32_t af[4][4], bf[4][4];
            #pragma unroll
            for (int mt = 0; mt < 4; mt++)
                ldsm_x4(af[mt], sA + (uint32_t)(rowA + mt * 16) * KPAD + kh * 32 + colK);
            #pragma unroll
            for (int ntp = 0; ntp < 4; ntp++)
                ldsm_x4(bf[ntp], sB + (uint32_t)(rowB + ntp * 16) * KPAD + kh * 32 + colK);
            #pragma unroll
            for (int mt = 0; mt < 4; mt++)
                #pragma unroll
                for (int nt = 0; nt < 8; nt++)
                    mma_f16acc(acc[mt][nt], af[mt],
                               bf[nt >> 1][nt & 1], bf[nt >> 1][2 + (nt & 1)]);
        }
    }

    const int er = m0 + wm + (lane >> 2);
    const int ec = n0 + wn + (lane & 3) * 2;
    #pragma unroll
    for (int mt = 0; mt < 4; mt++) {
        #pragma unroll
        for (int half = 0; half < 2; half++) {
            const int row = er + mt * 16 + half * 8;
            float s = 0.f, s2 = 0.f;
            #pragma unroll
            for (int nt = 0; nt < 8; nt++) {
                const int col = ec + nt * 8;
                float2 v = __half22float2(
                    *(const __half2*)&acc[mt][nt][half]);
                if (MODE == 1) {
                    __half2* dst = (row < 512)
                        ? (__half2*)(g_Y1h + (size_t)row * NT_ + col)
                        : (__half2*)(g_Hsh + (size_t)(row - 512) * NT_ + col);
                    *(uint32_t*)dst = acc[mt][nt][half];
                    s += v.x + v.y; s2 += v.x * v.x + v.y * v.y;
                } else {
                    const float bv = bias[row];
                    float2 h = __half22float2(
                        *(const __half2*)(g_Hsh + (size_t)row * NT_ + col));
                    *(__half2*)(g_Hfh + (size_t)row * NT_ + col) =
                        __floats2half2_rn(v.x + bv + h.x, v.y + bv + h.y);
                }
            }
            if (MODE == 1 && row < 512) {
                s  += __shfl_xor_sync(0xffffffffu, s, 1);
                s  += __shfl_xor_sync(0xffffffffu, s, 2);
                s2 += __shfl_xor_sync(0xffffffffu, s2, 1);
                s2 += __shfl_xor_sync(0xffffffffu, s2, 2);
                if ((lane & 3) == 0) {
                    atomicAdd(&g_bnsum[row], s);
                    atomicAdd(&g_bnsum2[row], s2);
                }
            }
        }
    }
}

// ---------------- Global path (coalesced via transposed weights) --------------
__global__ __launch_bounds__(512) void g_front(const float* __restrict__ gx)
{
    __shared__ float xs[CG_];
    const int b = blockIdx.x, tid = threadIdx.x;
    if (tid < CG_) xs[tid] = gx[b * CG_ + tid];
    __syncthreads();
    float a = 0.f, c = 0.f;
    #pragma unroll 4
    for (int k = 0; k < CG_; k++) {
        float xv = xs[k];
        a = fmaf(g_W1t[(size_t)k * MI_ + tid], xv, a);
        c = fmaf(g_Wst[(size_t)k * MI_ + tid], xv, c);
    }
    g_yg[b * MI_ + tid] = a;
    g_hg[b * MI_ + tid] = c;
}

__global__ __launch_bounds__(512) void g_tail(
    const float* __restrict__ gg1, const float* __restrict__ gb1,
    const float* __restrict__ gb2,
    const float* __restrict__ glng, const float* __restrict__ glnb)
{
    __shared__ float a[MI_];
    __shared__ float red[32];
    __shared__ float sh;
    const int b = blockIdx.x, o = threadIdx.x;

    float s = 0.f, s2 = 0.f;
    #pragma unroll
    for (int bb = 0; bb < B_; bb++) {
        float v = g_yg[bb * MI_ + o];
        s += v; s2 += v * v;
    }
    float mu  = s  * (1.f / 32.f);
    float var = s2 * (1.f / 32.f) - mu * mu;
    float sc  = rsqrtf(var + 1e-5f) * gg1[o];
    float shv = fmaf(-mu, sc, gb1[o]);
    a[o] = fmaxf(fmaf(g_yg[b * MI_ + o], sc, shv), 0.f);
    __syncthreads();

    float acc = 0.f;
    #pragma unroll 4
    for (int k = 0; k < MI_; k++)
        acc = fmaf(g_W2t[(size_t)k * MI_ + o], a[k], acc);
    float h = acc + gb2[o] + g_hg[b * MI_ + o];

    float ms = blockReduceSum(h, red);
    if (o == 0) sh = ms * (1.f / 512.f);
    __syncthreads();
    float lmu = sh;
    float d = h - lmu;
    float q = blockReduceSum(d * d, red);
    if (o == 0) sh = rsqrtf(q * (1.f / 512.f) + 1e-5f);
    __syncthreads();
    float lrs = sh;
    float z = fmaf(d * lrs, glng[o], glnb[o]);
    float n2 = blockReduceSum(z * z, red);
    if (o == 0) sh = rsqrtf(n2);
    __syncthreads();
    g_Ghat[b * MI_ + o] = z * sh;
}

// ---------------- fused LN + L2-normalize + similarity + loss partials --------
// Per block: 64 bt columns (same sample). 256 thr = 4 ty x 64 tx.
constexpr int LNU_GT   = 512 * 36;
constexpr int LNU_SMEM = (LNU_GT + 2 * 4 * 65 + 3 * 64 + 32 * 65) * 4;

__global__ __launch_bounds__(256) void ln_u(
    const float* __restrict__ lng, const float* __restrict__ lnb)
{
    extern __shared__ float sm[];
    float* sGT  = sm;                      // [512][36]; pass3-red overlays here
    float* r1   = sm + LNU_GT;             // [4][65]
    float* r2   = r1 + 4 * 65;
    float* mu_s = r2 + 4 * 65;             // [64]
    float* rs_s = mu_s + 64;
    float* rn_s = rs_s + 64;
    float* sE   = rn_s + 64;               // [32][65]

    const int q0 = blockIdx.x * 64;
    const int bblk = q0 >> 8;
    const int tid = threadIdx.x;
    const int tx = tid & 63, ty = tid >> 6;   // ty 0..3

    for (int i = tid; i < 512 * 32; i += 256) {
        int p = i & 511, n = i >> 9;
        sGT[p * 36 + n] = g_Ghat[n * MI_ + p];
    }

    const __half* base = g_Hfh + q0 + tx;

    float s = 0.f, s2 = 0.f;
    for (int p = ty; p < MI_; p += 4) {
        float v = __half2float(base[(size_t)p * NT_]);
        s += v; s2 += v * v;
    }
    r1[ty * 65 + tx] = s; r2[ty * 65 + tx] = s2;
    __syncthreads();
    if (ty == 0) {
        float a = 0.f, c = 0.f;
        #pragma unroll
        for (int i = 0; i < 4; i++) { a += r1[i * 65 + tx]; c += r2[i * 65 + tx]; }
        float mu  = a * (1.f / 512.f);
        float var = c * (1.f / 512.f) - mu * mu;
        mu_s[tx] = mu;
        rs_s[tx] = rsqrtf(var + 1e-5f);
    }
    __syncthreads();
    float mu = mu_s[tx], rs = rs_s[tx];

    float n2 = 0.f;
    for (int p = ty; p < MI_; p += 4) {
        float v = __half2float(base[(size_t)p * NT_]);
        float z = fmaf((v - mu) * rs, lng[p], lnb[p]);
        n2 += z * z;
    }
    __syncthreads();
    r1[ty * 65 + tx] = n2;
    __syncthreads();
    if (ty == 0) {
        float a = 0.f;
        #pragma unroll
        for (int i = 0; i < 4; i++) a += r1[i * 65 + tx];
        rn_s[tx] = rsqrtf(a);
    }
    __syncthreads();
    float rn = rn_s[tx];

    float accv[32];
    #pragma unroll
    for (int n = 0; n < 32; n++) accv[n] = 0.f;
    for (int p = ty; p < MI_; p += 4) {
        float v = __half2float(base[(size_t)p * NT_]);
        float z = fmaf((v - mu) * rs, lng[p], lnb[p]) * rn;
        const float* row = &sGT[p * 36];
        #pragma unroll
        for (int n4 = 0; n4 < 8; n4++) {
            float4 g = *(const float4*)(row + n4 * 4);
            accv[n4 * 4 + 0] = fmaf(z, g.x, accv[n4 * 4 + 0]);
            accv[n4 * 4 + 1] = fmaf(z, g.y, accv[n4 * 4 + 1]);
            accv[n4 * 4 + 2] = fmaf(z, g.z, accv[n4 * 4 + 2]);
            accv[n4 * 4 + 3] = fmaf(z, g.w, accv[n4 * 4 + 3]);
        }
    }

    __syncthreads();
    float* red = sGT;                      // reuse as [256][33]
    #pragma unroll
    for (int n = 0; n < 32; n++) red[(ty * 64 + tx) * 33 + n] = accv[n];
    __syncthreads();
    for (int j = tid; j < 2048; j += 256) {
        int txo = j & 63, n = j >> 6;
        float acc = 0.f;
        #pragma unroll
        for (int yy = 0; yy < 4; yy++) acc += red[(yy * 64 + txo) * 33 + n];
        if (n == bblk) {
            g_upos[n * T_ + (q0 & 255) + txo] = acc * (1.f / 0.07f);
        } else {
            sE[n * 65 + txo] = expf(acc - 1.0f);
        }
    }
    __syncthreads();
    if (tid < 32 && tid != bblk) {
        float t = 0.f;
        #pragma unroll
        for (int c = 0; c < 64; c++) t += sE[tid * 65 + c];
        atomicAdd(&g_S[tid], t);
    }
}

// ---------------- final loss (1 block) ----------------------------------------
__global__ __launch_bounds__(256) void loss_final(float* __restrict__ out)
{
    __shared__ float A[32];
    __shared__ float red[32];
    const int tid = threadIdx.x;
    if (tid < 32) A[tid] = 1.0f + logf(g_S[tid]);
    __syncthreads();
    float c = 0.f;
    for (int j = tid; j < NT_; j += 256) {
        int n = j >> 8;
        float p  = g_upos[j];
        float An = A[n];
        float mx = fmaxf(p, An);
        c += p - (mx + logf(expf(p - mx) + expf(An - mx)));
    }
    c = blockReduceSum(c, red);
    if (tid == 0) *out = -c / (float)NT_;
}

// ---------------- launch ------------------------------------------------------
extern "C" void kernel_launch(void* const* d_in, const int* in_sizes, int n_in,
                              void* d_out, int out_size)
{
    const float* x    = (const float*)d_in[0];
    const float* gx   = (const float*)d_in[1];
    const float* lW1  = (const float*)d_in[2];
    const float* lg1  = (const float*)d_in[3];
    const float* lb1  = (const float*)d_in[4];
    const float* lW2  = (const float*)d_in[5];
    const float* lb2  = (const float*)d_in[6];
    const float* lWs  = (const float*)d_in[7];
    const float* llng = (const float*)d_in[8];
    const float* llnb = (const float*)d_in[9];
    const float* gW1  = (const float*)d_in[10];
    const float* gg1  = (const float*)d_in[11];
    const float* gb1  = (const float*)d_in[12];
    const float* gW2  = (const float*)d_in[13];
    const float* gb2  = (const float*)d_in[14];
    const float* gWs  = (const float*)d_in[15];
    const float* glng = (const float*)d_in[16];
    const float* glnb = (const float*)d_in[17];
    float* out = (float*)d_out;

    cudaFuncSetAttribute(gemm_mma<1>, cudaFuncAttributeMaxDynamicSharedMemorySize, GEMM_SMEM);
    cudaFuncSetAttribute(gemm_mma<2>, cudaFuncAttributeMaxDynamicSharedMemorySize, GEMM_SMEM);
    cudaFuncSetAttribute(ln_u, cudaFuncAttributeMaxDynamicSharedMemorySize, LNU_SMEM);

    prep_all<<<5057, 256>>>(lW1, lWs, lW2, gW1, gWs, gW2, x);

    gemm_mma<1><<<dim3(32, 8), 256, GEMM_SMEM>>>(nullptr);
    split_y<<<dim3(128, 8), 256>>>(lg1, lb1);
    gemm_mma<2><<<dim3(32, 4), 256, GEMM_SMEM>>>(lb2);

    g_front<<<32, 512>>>(gx);
    g_tail<<<32, 512>>>(gg1, gb1, gb2, glng, glnb);

    ln_u<<<128, 256, LNU_SMEM>>>(llng, llnb);
    loss_final<<<1, 256>>>(out);
}